// round 1
// baseline (speedup 1.0000x reference)
#include <cuda_runtime.h>

#define BB 2
#define EE 1024
#define TT 2048
#define HH 16
#define DHH 64

// Scratch (static device arrays: allocation-free rule)
__device__ float g_qp[BB*EE*TT];                 // 16 MB
__device__ float g_kp[BB*EE*TT];                 // 16 MB
__device__ float g_vp[BB*EE*TT];                 // 16 MB
__device__ float g_o [BB*EE*TT];                 // 16 MB
__device__ float g_att[(size_t)BB*HH*TT*TT];     // 512 MB

// ---------------------------------------------------------------------------
// conv1x1 GEMM: Y[b,o,t] = mask[b,t] * sum_c W[o,c]*X[b,c,t] + bias[o]
// 128x128 block tile, BK=16, 256 threads, 8x8 per thread.
// ---------------------------------------------------------------------------
__device__ __forceinline__ void gemm_conv(
    const float* __restrict__ W, const float* __restrict__ X,
    const float* __restrict__ bias, const float* __restrict__ mask,
    float* __restrict__ Y, int b)
{
    __shared__ float Ws[16][132];
    __shared__ float Xs[16][132];
    const int tid = threadIdx.x;
    const int tx  = tid & 15;
    const int ty  = tid >> 4;
    const int o0  = blockIdx.y * 128;
    const int t0  = blockIdx.x * 128;
    const float* Xb = X + (size_t)b * EE * TT;

    float acc[8][8];
    #pragma unroll
    for (int i = 0; i < 8; i++)
        #pragma unroll
        for (int j = 0; j < 8; j++) acc[i][j] = 0.f;

    for (int k0 = 0; k0 < EE; k0 += 16) {
        #pragma unroll
        for (int l = 0; l < 2; l++) {
            int idx = tid + l * 256;            // [0,512) float4 index
            int wr  = idx >> 2;                 // 0..127
            int wc  = (idx & 3) * 4;            // 0..12
            float4 w4 = *(const float4*)&W[(size_t)(o0 + wr) * EE + k0 + wc];
            Ws[wc+0][wr] = w4.x; Ws[wc+1][wr] = w4.y;
            Ws[wc+2][wr] = w4.z; Ws[wc+3][wr] = w4.w;
            int xr = idx >> 5;                  // 0..15
            int xc = (idx & 31) * 4;            // 0..124
            *(float4*)&Xs[xr][xc] =
                *(const float4*)&Xb[(size_t)(k0 + xr) * TT + t0 + xc];
        }
        __syncthreads();
        #pragma unroll
        for (int kk = 0; kk < 16; kk++) {
            float4 A0 = *(const float4*)&Ws[kk][ty*4];
            float4 A1 = *(const float4*)&Ws[kk][64 + ty*4];
            float4 B0 = *(const float4*)&Xs[kk][tx*4];
            float4 B1 = *(const float4*)&Xs[kk][64 + tx*4];
            float av[8] = {A0.x,A0.y,A0.z,A0.w,A1.x,A1.y,A1.z,A1.w};
            float bv[8] = {B0.x,B0.y,B0.z,B0.w,B1.x,B1.y,B1.z,B1.w};
            #pragma unroll
            for (int i = 0; i < 8; i++)
                #pragma unroll
                for (int j = 0; j < 8; j++)
                    acc[i][j] += av[i] * bv[j];
        }
        __syncthreads();
    }

    #pragma unroll
    for (int i = 0; i < 8; i++) {
        int o = o0 + (i >> 2) * 64 + ty * 4 + (i & 3);
        float bia = bias[o];
        #pragma unroll
        for (int j = 0; j < 8; j++) {
            int t = t0 + (j >> 2) * 64 + tx * 4 + (j & 3);
            Y[(size_t)b * EE * TT + (size_t)o * TT + t] =
                mask[(size_t)b * TT + t] * acc[i][j] + bia;
        }
    }
}

__global__ void __launch_bounds__(256)
conv3_kernel(const float* __restrict__ q, const float* __restrict__ k,
             const float* __restrict__ v,
             const float* __restrict__ qm, const float* __restrict__ km,
             const float* __restrict__ vm,
             const float* __restrict__ Wq, const float* __restrict__ bq,
             const float* __restrict__ Wk, const float* __restrict__ bk,
             const float* __restrict__ Wv, const float* __restrict__ bv)
{
    int m = blockIdx.z >> 1;
    int b = blockIdx.z & 1;
    if (m == 0)      gemm_conv(Wq, q, bq, qm, g_qp, b);
    else if (m == 1) gemm_conv(Wk, k, bk, km, g_kp, b);
    else             gemm_conv(Wv, v, bv, vm, g_vp, b);
}

__global__ void __launch_bounds__(256)
conv_final_kernel(const float* __restrict__ Wo, const float* __restrict__ bo,
                  const float* __restrict__ km, float* __restrict__ out)
{
    gemm_conv(Wo, g_o, bo, km, out, blockIdx.z);
}

// ---------------------------------------------------------------------------
// Scores + softmax. Block = 64 q-rows of one (b,h). Loops k in chunks of 128.
// Pass 1: S = (Q^T K) * qm*km/32 -> raw to g_att, online row max/sum.
// Pass 2: re-read own chunk (L2-hot), write exp(s-m)/l * km.
// ---------------------------------------------------------------------------
__global__ void __launch_bounds__(256)
scores_kernel(const float* __restrict__ qmask, const float* __restrict__ kmask)
{
    const int b  = blockIdx.z;
    const int h  = blockIdx.y;
    const int qt = blockIdx.x;
    const int q0 = qt * 64;

    const float* Q = g_qp + ((size_t)b * EE + h * DHH) * TT;
    const float* K = g_kp + ((size_t)b * EE + h * DHH) * TT;
    float* A = g_att + ((size_t)b * HH + h) * TT * TT;

    __shared__ float Qs[64][68];    // [d][q]
    __shared__ float Ks[64][132];   // [d][k]

    const int tid = threadIdx.x;
    const int tx  = tid & 15;   // k groups: 8 cols each
    const int ty  = tid >> 4;   // q groups: 4 rows each

    // load Q tile 64(d) x 64(q)
    #pragma unroll
    for (int l = 0; l < 4; l++) {
        int idx = tid + l * 256;       // [0,1024) float4 idx
        int d   = idx >> 4;
        int qq  = (idx & 15) * 4;
        *(float4*)&Qs[d][qq] = *(const float4*)&Q[(size_t)d * TT + q0 + qq];
    }

    float qm[4];
    #pragma unroll
    for (int i = 0; i < 4; i++) qm[i] = qmask[(size_t)b * TT + q0 + ty * 4 + i];

    float mrow[4], lrow[4];
    #pragma unroll
    for (int i = 0; i < 4; i++) { mrow[i] = -1e30f; lrow[i] = 0.f; }

    const float scale = 0.03125f;  // 1/sqrt(1024)

    for (int kc = 0; kc < TT; kc += 128) {
        __syncthreads();
        #pragma unroll
        for (int l = 0; l < 8; l++) {
            int idx = tid + l * 256;   // [0,2048) float4 idx
            int d   = idx >> 5;
            int kk  = (idx & 31) * 4;
            *(float4*)&Ks[d][kk] = *(const float4*)&K[(size_t)d * TT + kc + kk];
        }
        __syncthreads();

        float s[4][8];
        #pragma unroll
        for (int i = 0; i < 4; i++)
            #pragma unroll
            for (int j = 0; j < 8; j++) s[i][j] = 0.f;

        #pragma unroll 8
        for (int d = 0; d < 64; d++) {
            float4 QV = *(const float4*)&Qs[d][ty * 4];
            float4 K0 = *(const float4*)&Ks[d][tx * 8];
            float4 K1 = *(const float4*)&Ks[d][tx * 8 + 4];
            float qv[4] = {QV.x, QV.y, QV.z, QV.w};
            float kv[8] = {K0.x,K0.y,K0.z,K0.w,K1.x,K1.y,K1.z,K1.w};
            #pragma unroll
            for (int i = 0; i < 4; i++)
                #pragma unroll
                for (int j = 0; j < 8; j++)
                    s[i][j] += qv[i] * kv[j];
        }

        float km[8];
        #pragma unroll
        for (int j = 0; j < 8; j++)
            km[j] = kmask[(size_t)b * TT + kc + tx * 8 + j];

        #pragma unroll
        for (int i = 0; i < 4; i++)
            #pragma unroll
            for (int j = 0; j < 8; j++)
                s[i][j] *= qm[i] * km[j] * scale;

        // spill raw scores
        #pragma unroll
        for (int i = 0; i < 4; i++) {
            size_t off = (size_t)(q0 + ty * 4 + i) * TT + kc + tx * 8;
            float4 w0 = make_float4(s[i][0], s[i][1], s[i][2], s[i][3]);
            float4 w1 = make_float4(s[i][4], s[i][5], s[i][6], s[i][7]);
            *(float4*)&A[off]     = w0;
            *(float4*)&A[off + 4] = w1;
        }

        // online softmax stats per q-row (reduce across the 16 tx threads)
        #pragma unroll
        for (int i = 0; i < 4; i++) {
            float cm = s[i][0];
            #pragma unroll
            for (int j = 1; j < 8; j++) cm = fmaxf(cm, s[i][j]);
            cm = fmaxf(cm, __shfl_xor_sync(0xffffffffu, cm, 1));
            cm = fmaxf(cm, __shfl_xor_sync(0xffffffffu, cm, 2));
            cm = fmaxf(cm, __shfl_xor_sync(0xffffffffu, cm, 4));
            cm = fmaxf(cm, __shfl_xor_sync(0xffffffffu, cm, 8));
            float mn = fmaxf(mrow[i], cm);
            float cs = 0.f;
            #pragma unroll
            for (int j = 0; j < 8; j++) cs += __expf(s[i][j] - mn);
            cs += __shfl_xor_sync(0xffffffffu, cs, 1);
            cs += __shfl_xor_sync(0xffffffffu, cs, 2);
            cs += __shfl_xor_sync(0xffffffffu, cs, 4);
            cs += __shfl_xor_sync(0xffffffffu, cs, 8);
            lrow[i] = lrow[i] * __expf(mrow[i] - mn) + cs;
            mrow[i] = mn;
        }
    }

    float rl[4];
    #pragma unroll
    for (int i = 0; i < 4; i++) rl[i] = 1.0f / lrow[i];

    // Pass 2: normalize in place (same thread reads what it wrote)
    for (int kc = 0; kc < TT; kc += 128) {
        float km[8];
        #pragma unroll
        for (int j = 0; j < 8; j++)
            km[j] = kmask[(size_t)b * TT + kc + tx * 8 + j];
        #pragma unroll
        for (int i = 0; i < 4; i++) {
            size_t off = (size_t)(q0 + ty * 4 + i) * TT + kc + tx * 8;
            float4 s0 = *(const float4*)&A[off];
            float4 s1 = *(const float4*)&A[off + 4];
            float4 a0, a1;
            a0.x = __expf(s0.x - mrow[i]) * rl[i] * km[0];
            a0.y = __expf(s0.y - mrow[i]) * rl[i] * km[1];
            a0.z = __expf(s0.z - mrow[i]) * rl[i] * km[2];
            a0.w = __expf(s0.w - mrow[i]) * rl[i] * km[3];
            a1.x = __expf(s1.x - mrow[i]) * rl[i] * km[4];
            a1.y = __expf(s1.y - mrow[i]) * rl[i] * km[5];
            a1.z = __expf(s1.z - mrow[i]) * rl[i] * km[6];
            a1.w = __expf(s1.w - mrow[i]) * rl[i] * km[7];
            *(float4*)&A[off]     = a0;
            *(float4*)&A[off + 4] = a1;
        }
    }
}

// ---------------------------------------------------------------------------
// O[b,h,d,k] = sum_q V[b,h,d,q] * A[b,h,q,k].  Block: 64(d) x 128(k) tile.
// ---------------------------------------------------------------------------
__global__ void __launch_bounds__(256)
av_kernel()
{
    const int b  = blockIdx.z;
    const int h  = blockIdx.y;
    const int k0 = blockIdx.x * 128;

    const float* V = g_vp + ((size_t)b * EE + h * DHH) * TT;
    const float* A = g_att + ((size_t)b * HH + h) * TT * TT;
    float* O = g_o + ((size_t)b * EE + h * DHH) * TT;

    __shared__ float Vs[32][68];    // [q][d]
    __shared__ float As[32][132];   // [q][k]

    const int tid = threadIdx.x;
    const int tx  = tid & 15;   // k: 8 each
    const int ty  = tid >> 4;   // d: 4 each

    float acc[4][8];
    #pragma unroll
    for (int i = 0; i < 4; i++)
        #pragma unroll
        for (int j = 0; j < 8; j++) acc[i][j] = 0.f;

    for (int qc = 0; qc < TT; qc += 32) {
        __syncthreads();
        #pragma unroll
        for (int l = 0; l < 2; l++) {
            int idx = tid + l * 256;     // [0,512) float4 idx over V tile
            int d   = idx >> 3;          // 0..63
            int q4  = (idx & 7) * 4;     // 0..28
            float4 v4 = *(const float4*)&V[(size_t)d * TT + qc + q4];
            Vs[q4+0][d] = v4.x; Vs[q4+1][d] = v4.y;
            Vs[q4+2][d] = v4.z; Vs[q4+3][d] = v4.w;
        }
        #pragma unroll
        for (int l = 0; l < 4; l++) {
            int idx = tid + l * 256;     // [0,1024) float4 idx over A tile
            int q   = idx >> 5;          // 0..31
            int k4  = (idx & 31) * 4;    // 0..124
            *(float4*)&As[q][k4] =
                *(const float4*)&A[(size_t)(qc + q) * TT + k0 + k4];
        }
        __syncthreads();

        #pragma unroll 8
        for (int q = 0; q < 32; q++) {
            float4 VV = *(const float4*)&Vs[q][ty * 4];
            float4 B0 = *(const float4*)&As[q][tx * 8];
            float4 B1 = *(const float4*)&As[q][tx * 8 + 4];
            float vv[4] = {VV.x, VV.y, VV.z, VV.w};
            float bv[8] = {B0.x,B0.y,B0.z,B0.w,B1.x,B1.y,B1.z,B1.w};
            #pragma unroll
            for (int i = 0; i < 4; i++)
                #pragma unroll
                for (int j = 0; j < 8; j++)
                    acc[i][j] += vv[i] * bv[j];
        }
    }

    #pragma unroll
    for (int i = 0; i < 4; i++) {
        int d = ty * 4 + i;
        size_t off = (size_t)d * TT + k0 + tx * 8;
        float4 w0 = make_float4(acc[i][0], acc[i][1], acc[i][2], acc[i][3]);
        float4 w1 = make_float4(acc[i][4], acc[i][5], acc[i][6], acc[i][7]);
        *(float4*)&O[off]     = w0;
        *(float4*)&O[off + 4] = w1;
    }
}

// ---------------------------------------------------------------------------
extern "C" void kernel_launch(void* const* d_in, const int* in_sizes, int n_in,
                              void* d_out, int out_size)
{
    const float* q   = (const float*)d_in[0];
    const float* k   = (const float*)d_in[1];
    const float* v   = (const float*)d_in[2];
    const float* qm  = (const float*)d_in[3];
    const float* km  = (const float*)d_in[4];
    const float* vm  = (const float*)d_in[5];
    const float* Wq  = (const float*)d_in[6];
    const float* bq  = (const float*)d_in[7];
    const float* Wk  = (const float*)d_in[8];
    const float* bk  = (const float*)d_in[9];
    const float* Wv  = (const float*)d_in[10];
    const float* bv  = (const float*)d_in[11];
    const float* Wo  = (const float*)d_in[12];
    const float* bo  = (const float*)d_in[13];
    float* out = (float*)d_out;

    dim3 g1(TT / 128, EE / 128, 3 * BB);
    conv3_kernel<<<g1, 256>>>(q, k, v, qm, km, vm, Wq, bq, Wk, bk, Wv, bv);

    dim3 g2(TT / 64, HH, BB);
    scores_kernel<<<g2, 256>>>(qm, km);

    dim3 g3(TT / 128, HH, BB);
    av_kernel<<<g3, 256>>>();

    dim3 g4(TT / 128, EE / 128, BB);
    conv_final_kernel<<<g4, 256>>>(Wo, bo, km, out);
}

// round 2
// speedup vs baseline: 3.0399x; 3.0399x over previous
#include <cuda_runtime.h>

#define BB 2
#define EE 1024
#define TT 2048
#define HH 16
#define DHH 64
#define SCALE 0.03125f

// Scratch (static device arrays: allocation-free rule)
__device__ float g_qp[BB*EE*TT];                 // 16 MB
__device__ float g_kp[BB*EE*TT];                 // 16 MB
__device__ float g_vp[BB*EE*TT];                 // 16 MB
__device__ float g_o [BB*EE*TT];                 // 16 MB
__device__ float g_att[(size_t)BB*HH*TT*TT];     // 512 MB (unnormalized exp(s)*km)
__device__ float g_rl [BB*HH*TT];                // 1/l per (b,h,q)

__device__ __forceinline__ unsigned f2tf(float x){
    unsigned u; asm("cvt.rna.tf32.f32 %0, %1;" : "=r"(u) : "f"(x)); return u;
}

__device__ __forceinline__ void mma8(float c[4], const unsigned a[4], const unsigned b[2]){
    asm volatile("mma.sync.aligned.m16n8k8.row.col.f32.tf32.tf32.f32 "
        "{%0,%1,%2,%3},{%4,%5,%6,%7},{%8,%9},{%0,%1,%2,%3};"
        : "+f"(c[0]),"+f"(c[1]),"+f"(c[2]),"+f"(c[3])
        : "r"(a[0]),"r"(a[1]),"r"(a[2]),"r"(a[3]),"r"(b[0]),"r"(b[1]));
}

// ---------------------------------------------------------------------------
// conv1x1: Y[b,o,t] = mask[b,t]*sum_c W[o,c]X[b,c,t] + bias[o]
// Tile 128(o) x 128(t), K staged 32. 8 warps = 4(m) x 2(n), warp 32x64.
// ---------------------------------------------------------------------------
__device__ __forceinline__ void gemm_conv_tf32(
    const float* __restrict__ W, const float* __restrict__ X,
    const float* __restrict__ bias, const float* __restrict__ mask,
    float* __restrict__ Y, int b)
{
    __shared__ unsigned Ws[128][36];   // [m=o][k=c]
    __shared__ unsigned Xs[32][136];   // [k=c][n=t]

    const int tid = threadIdx.x, lane = tid & 31, warp = tid >> 5;
    const int g = lane >> 2, t4 = lane & 3;
    const int wm = warp >> 1, wn = warp & 1;
    const int o0 = blockIdx.y * 128, t0 = blockIdx.x * 128;
    const float* Xb = X + (size_t)b * EE * TT;

    float acc[2][8][4];
    #pragma unroll
    for (int i = 0; i < 2; i++)
        #pragma unroll
        for (int j = 0; j < 8; j++)
            #pragma unroll
            for (int e = 0; e < 4; e++) acc[i][j][e] = 0.f;

    for (int k0 = 0; k0 < EE; k0 += 32) {
        #pragma unroll
        for (int l = 0; l < 4; l++) {
            int idx = tid + l * 256;            // 1024 float4 over W tile
            int o = idx >> 3, c = (idx & 7) * 4;
            float4 w4 = *(const float4*)&W[(size_t)(o0 + o) * EE + k0 + c];
            Ws[o][c+0] = f2tf(w4.x); Ws[o][c+1] = f2tf(w4.y);
            Ws[o][c+2] = f2tf(w4.z); Ws[o][c+3] = f2tf(w4.w);
        }
        #pragma unroll
        for (int l = 0; l < 4; l++) {
            int idx = tid + l * 256;            // 1024 float4 over X tile
            int c = idx >> 5, t = (idx & 31) * 4;
            float4 x4 = *(const float4*)&Xb[(size_t)(k0 + c) * TT + t0 + t];
            Xs[c][t+0] = f2tf(x4.x); Xs[c][t+1] = f2tf(x4.y);
            Xs[c][t+2] = f2tf(x4.z); Xs[c][t+3] = f2tf(x4.w);
        }
        __syncthreads();

        #pragma unroll
        for (int kk = 0; kk < 32; kk += 8) {
            unsigned a[2][4], bf[8][2];
            #pragma unroll
            for (int mt = 0; mt < 2; mt++) {
                int m = wm * 32 + mt * 16;
                a[mt][0] = Ws[m + g    ][kk + t4];
                a[mt][1] = Ws[m + g + 8][kk + t4];
                a[mt][2] = Ws[m + g    ][kk + t4 + 4];
                a[mt][3] = Ws[m + g + 8][kk + t4 + 4];
            }
            #pragma unroll
            for (int nt = 0; nt < 8; nt++) {
                int n = wn * 64 + nt * 8 + g;
                bf[nt][0] = Xs[kk + t4    ][n];
                bf[nt][1] = Xs[kk + t4 + 4][n];
            }
            #pragma unroll
            for (int mt = 0; mt < 2; mt++)
                #pragma unroll
                for (int nt = 0; nt < 8; nt++)
                    mma8(acc[mt][nt], a[mt], bf[nt]);
        }
        __syncthreads();
    }

    #pragma unroll
    for (int mt = 0; mt < 2; mt++) {
        int o_lo = o0 + wm * 32 + mt * 16 + g;
        float b_lo = bias[o_lo], b_hi = bias[o_lo + 8];
        #pragma unroll
        for (int nt = 0; nt < 8; nt++) {
            int t = t0 + wn * 64 + nt * 8 + 2 * t4;
            float mk0 = mask[(size_t)b * TT + t];
            float mk1 = mask[(size_t)b * TT + t + 1];
            float2 v0 = make_float2(mk0 * acc[mt][nt][0] + b_lo,
                                    mk1 * acc[mt][nt][1] + b_lo);
            float2 v1 = make_float2(mk0 * acc[mt][nt][2] + b_hi,
                                    mk1 * acc[mt][nt][3] + b_hi);
            *(float2*)&Y[(size_t)b * EE * TT + (size_t)o_lo * TT + t]       = v0;
            *(float2*)&Y[(size_t)b * EE * TT + (size_t)(o_lo + 8) * TT + t] = v1;
        }
    }
}

__global__ void __launch_bounds__(256)
conv3_kernel(const float* __restrict__ q, const float* __restrict__ k,
             const float* __restrict__ v,
             const float* __restrict__ qm, const float* __restrict__ km,
             const float* __restrict__ vm,
             const float* __restrict__ Wq, const float* __restrict__ bq,
             const float* __restrict__ Wk, const float* __restrict__ bk,
             const float* __restrict__ Wv, const float* __restrict__ bv)
{
    int m = blockIdx.z >> 1;
    int b = blockIdx.z & 1;
    if (m == 0)      gemm_conv_tf32(Wq, q, bq, qm, g_qp, b);
    else if (m == 1) gemm_conv_tf32(Wk, k, bk, km, g_kp, b);
    else             gemm_conv_tf32(Wv, v, bv, vm, g_vp, b);
}

__global__ void __launch_bounds__(256)
conv_final_kernel(const float* __restrict__ Wo, const float* __restrict__ bo,
                  const float* __restrict__ km, float* __restrict__ out)
{
    gemm_conv_tf32(Wo, g_o, bo, km, out, blockIdx.z);
}

// ---------------------------------------------------------------------------
// Scores: per (b,h, 64 q rows). S = Q^T K (K-dim = 64). Single pass:
//   P[q,k] = exp(s*qm*km*scale) * km  stored unnormalized; l_q accumulated.
// No max subtraction needed: |s*scale| <~ 3 (safe for exp).
// 8 warps = 4(m:q) x 2(n:k); warp 16q x 32k; k chunks of 64.
// ---------------------------------------------------------------------------
__global__ void __launch_bounds__(256)
scores_tf32(const float* __restrict__ qmask, const float* __restrict__ kmask)
{
    const int b = blockIdx.z, h = blockIdx.y, q0 = blockIdx.x * 64;
    const float* Q = g_qp + ((size_t)b * EE + h * DHH) * TT;
    const float* K = g_kp + ((size_t)b * EE + h * DHH) * TT;
    float* P = g_att + (size_t)(b * HH + h) * TT * TT;

    __shared__ unsigned Qs[64][68];   // [m=q][k=d]
    __shared__ unsigned Ks[64][72];   // [k=d][n=kcol]
    __shared__ float kmc[64];
    __shared__ float lw[4][2][16];

    const int tid = threadIdx.x, lane = tid & 31, warp = tid >> 5;
    const int g = lane >> 2, t4 = lane & 3;
    const int wm = warp >> 1, wn = warp & 1;
    const int wq = wm * 16;

    // stage Q tile transposed: Qs[q][d]
    #pragma unroll
    for (int l = 0; l < 4; l++) {
        int idx = tid + l * 256;          // 1024 float4 over 64d x 64q
        int d = idx >> 4, q4 = (idx & 15) * 4;
        float4 v = *(const float4*)&Q[(size_t)d * TT + q0 + q4];
        Qs[q4+0][d] = f2tf(v.x); Qs[q4+1][d] = f2tf(v.y);
        Qs[q4+2][d] = f2tf(v.z); Qs[q4+3][d] = f2tf(v.w);
    }
    __syncthreads();

    // preload A fragments (Q) for all 8 k-steps — resident across all chunks
    unsigned areg[8][4];
    #pragma unroll
    for (int ks = 0; ks < 8; ks++) {
        areg[ks][0] = Qs[wq + g    ][ks * 8 + t4];
        areg[ks][1] = Qs[wq + g + 8][ks * 8 + t4];
        areg[ks][2] = Qs[wq + g    ][ks * 8 + t4 + 4];
        areg[ks][3] = Qs[wq + g + 8][ks * 8 + t4 + 4];
    }

    const float qm0 = qmask[(size_t)b * TT + q0 + wq + g];
    const float qm1 = qmask[(size_t)b * TT + q0 + wq + g + 8];
    float l0 = 0.f, l1 = 0.f;

    for (int kc = 0; kc < TT; kc += 64) {
        __syncthreads();
        #pragma unroll
        for (int l = 0; l < 4; l++) {
            int idx = tid + l * 256;      // 1024 float4 over 64d x 64k
            int d = idx >> 4, k4 = (idx & 15) * 4;
            float4 v = *(const float4*)&K[(size_t)d * TT + kc + k4];
            Ks[d][k4+0] = f2tf(v.x); Ks[d][k4+1] = f2tf(v.y);
            Ks[d][k4+2] = f2tf(v.z); Ks[d][k4+3] = f2tf(v.w);
        }
        if (tid < 64) kmc[tid] = kmask[(size_t)b * TT + kc + tid];
        __syncthreads();

        float s[4][4];
        #pragma unroll
        for (int nt = 0; nt < 4; nt++)
            #pragma unroll
            for (int e = 0; e < 4; e++) s[nt][e] = 0.f;

        #pragma unroll
        for (int ks = 0; ks < 8; ks++) {
            #pragma unroll
            for (int nt = 0; nt < 4; nt++) {
                unsigned bf[2];
                int n = wn * 32 + nt * 8 + g;
                bf[0] = Ks[ks * 8 + t4    ][n];
                bf[1] = Ks[ks * 8 + t4 + 4][n];
                mma8(s[nt], areg[ks], bf);
            }
        }

        #pragma unroll
        for (int nt = 0; nt < 4; nt++) {
            int kcol = wn * 32 + nt * 8 + 2 * t4;
            float km0 = kmc[kcol], km1 = kmc[kcol + 1];
            float e00 = __expf(s[nt][0] * (qm0 * km0 * SCALE));
            float e01 = __expf(s[nt][1] * (qm0 * km1 * SCALE));
            float e10 = __expf(s[nt][2] * (qm1 * km0 * SCALE));
            float e11 = __expf(s[nt][3] * (qm1 * km1 * SCALE));
            l0 += e00 + e01;
            l1 += e10 + e11;
            size_t r0 = (size_t)(q0 + wq + g) * TT + kc + kcol;
            size_t r1 = (size_t)(q0 + wq + g + 8) * TT + kc + kcol;
            *(float2*)&P[r0] = make_float2(e00 * km0, e01 * km1);
            *(float2*)&P[r1] = make_float2(e10 * km0, e11 * km1);
        }
    }

    // reduce l over quad lanes (t4) then across the 2 n-warps
    l0 += __shfl_xor_sync(0xffffffffu, l0, 1);
    l0 += __shfl_xor_sync(0xffffffffu, l0, 2);
    l1 += __shfl_xor_sync(0xffffffffu, l1, 1);
    l1 += __shfl_xor_sync(0xffffffffu, l1, 2);
    if (t4 == 0) { lw[wm][wn][g] = l0; lw[wm][wn][g + 8] = l1; }
    __syncthreads();
    if (tid < 64) {
        float l = lw[tid >> 4][0][tid & 15] + lw[tid >> 4][1][tid & 15];
        g_rl[(size_t)(b * HH + h) * TT + q0 + tid] = 1.0f / l;
    }
}

// ---------------------------------------------------------------------------
// AV: O[d,k] = sum_q (V[d,q]*rl_q) * P[q,k].  M=64(d), N=128(k) tile, K=q
// staged 32. 8 warps = 2(m) x 4(n); warp 32d x 32k.
// ---------------------------------------------------------------------------
__global__ void __launch_bounds__(256)
av_tf32()
{
    const int b = blockIdx.z, h = blockIdx.y, k0 = blockIdx.x * 128;
    const float* V  = g_vp  + ((size_t)b * EE + h * DHH) * TT;
    const float* P  = g_att + (size_t)(b * HH + h) * TT * TT;
    const float* RL = g_rl  + (size_t)(b * HH + h) * TT;
    float* O = g_o + ((size_t)b * EE + h * DHH) * TT;

    __shared__ unsigned Vs[64][36];    // [m=d][k=q]
    __shared__ unsigned Ps[32][136];   // [k=q][n=kcol]

    const int tid = threadIdx.x, lane = tid & 31, warp = tid >> 5;
    const int g = lane >> 2, t4 = lane & 3;
    const int wm = warp >> 2, wn = warp & 3;

    float acc[2][4][4];
    #pragma unroll
    for (int i = 0; i < 2; i++)
        #pragma unroll
        for (int j = 0; j < 4; j++)
            #pragma unroll
            for (int e = 0; e < 4; e++) acc[i][j][e] = 0.f;

    for (int qc = 0; qc < TT; qc += 32) {
        __syncthreads();
        #pragma unroll
        for (int l = 0; l < 2; l++) {
            int idx = tid + l * 256;       // 512 float4 over 64d x 32q
            int d = idx >> 3, q4 = (idx & 7) * 4;
            float4 v = *(const float4*)&V[(size_t)d * TT + qc + q4];
            float4 r = *(const float4*)&RL[qc + q4];
            Vs[d][q4+0] = f2tf(v.x * r.x); Vs[d][q4+1] = f2tf(v.y * r.y);
            Vs[d][q4+2] = f2tf(v.z * r.z); Vs[d][q4+3] = f2tf(v.w * r.w);
        }
        #pragma unroll
        for (int l = 0; l < 4; l++) {
            int idx = tid + l * 256;       // 1024 float4 over 32q x 128k
            int qq = idx >> 5, k4 = (idx & 31) * 4;
            float4 v = *(const float4*)&P[(size_t)(qc + qq) * TT + k0 + k4];
            Ps[qq][k4+0] = f2tf(v.x); Ps[qq][k4+1] = f2tf(v.y);
            Ps[qq][k4+2] = f2tf(v.z); Ps[qq][k4+3] = f2tf(v.w);
        }
        __syncthreads();

        #pragma unroll
        for (int ks = 0; ks < 4; ks++) {
            unsigned a[2][4], bf[4][2];
            #pragma unroll
            for (int mt = 0; mt < 2; mt++) {
                int m = wm * 32 + mt * 16;
                a[mt][0] = Vs[m + g    ][ks * 8 + t4];
                a[mt][1] = Vs[m + g + 8][ks * 8 + t4];
                a[mt][2] = Vs[m + g    ][ks * 8 + t4 + 4];
                a[mt][3] = Vs[m + g + 8][ks * 8 + t4 + 4];
            }
            #pragma unroll
            for (int nt = 0; nt < 4; nt++) {
                int n = wn * 32 + nt * 8 + g;
                bf[nt][0] = Ps[ks * 8 + t4    ][n];
                bf[nt][1] = Ps[ks * 8 + t4 + 4][n];
            }
            #pragma unroll
            for (int mt = 0; mt < 2; mt++)
                #pragma unroll
                for (int nt = 0; nt < 4; nt++)
                    mma8(acc[mt][nt], a[mt], bf[nt]);
        }
    }

    #pragma unroll
    for (int mt = 0; mt < 2; mt++) {
        int d = wm * 32 + mt * 16 + g;
        #pragma unroll
        for (int nt = 0; nt < 4; nt++) {
            int kcol = k0 + wn * 32 + nt * 8 + 2 * t4;
            *(float2*)&O[(size_t)d * TT + kcol] =
                make_float2(acc[mt][nt][0], acc[mt][nt][1]);
            *(float2*)&O[(size_t)(d + 8) * TT + kcol] =
                make_float2(acc[mt][nt][2], acc[mt][nt][3]);
        }
    }
}

// ---------------------------------------------------------------------------
extern "C" void kernel_launch(void* const* d_in, const int* in_sizes, int n_in,
                              void* d_out, int out_size)
{
    const float* q   = (const float*)d_in[0];
    const float* k   = (const float*)d_in[1];
    const float* v   = (const float*)d_in[2];
    const float* qm  = (const float*)d_in[3];
    const float* km  = (const float*)d_in[4];
    const float* vm  = (const float*)d_in[5];
    const float* Wq  = (const float*)d_in[6];
    const float* bq  = (const float*)d_in[7];
    const float* Wk  = (const float*)d_in[8];
    const float* bk  = (const float*)d_in[9];
    const float* Wv  = (const float*)d_in[10];
    const float* bv  = (const float*)d_in[11];
    const float* Wo  = (const float*)d_in[12];
    const float* bo  = (const float*)d_in[13];
    float* out = (float*)d_out;

    dim3 g1(TT / 128, EE / 128, 3 * BB);
    conv3_kernel<<<g1, 256>>>(q, k, v, qm, km, vm, Wq, bq, Wk, bk, Wv, bv);

    dim3 g2(TT / 64, HH, BB);
    scores_tf32<<<g2, 256>>>(qm, km);

    dim3 g3(TT / 128, HH, BB);
    av_tf32<<<g3, 256>>>();

    dim3 g4(TT / 128, EE / 128, BB);
    conv_final_kernel<<<g4, 256>>>(Wo, bo, km, out);
}

// round 3
// speedup vs baseline: 3.4332x; 1.1294x over previous
#include <cuda_runtime.h>

#define BB 2
#define EE 1024
#define TT 2048
#define HH 16
#define DHH 64
#define SCALE 0.03125f

// Scratch (static device arrays: allocation-free rule)
__device__ float g_qp[BB*EE*TT];                 // 16 MB
__device__ float g_kp[BB*EE*TT];                 // 16 MB
__device__ float g_vp[BB*EE*TT];                 // 16 MB
__device__ float g_o [BB*EE*TT];                 // 16 MB
__device__ float g_att[(size_t)BB*HH*TT*TT];     // 512 MB (unnormalized exp(s)*km)
__device__ float g_rl [BB*HH*TT];                // 1/l per (b,h,q)

__device__ __forceinline__ unsigned f2tf(float x){
    unsigned u; asm("cvt.rna.tf32.f32 %0, %1;" : "=r"(u) : "f"(x)); return u;
}

__device__ __forceinline__ void mma8(float c[4], const unsigned a[4], const unsigned b[2]){
    asm volatile("mma.sync.aligned.m16n8k8.row.col.f32.tf32.tf32.f32 "
        "{%0,%1,%2,%3},{%4,%5,%6,%7},{%8,%9},{%0,%1,%2,%3};"
        : "+f"(c[0]),"+f"(c[1]),"+f"(c[2]),"+f"(c[3])
        : "r"(a[0]),"r"(a[1]),"r"(a[2]),"r"(a[3]),"r"(b[0]),"r"(b[1]));
}

// ===========================================================================
// conv1x1: Y[b,o,t] = mask[b,t]*sum_c W[o,c]X[b,c,t] + bias[o]
// 128(o) x 128(t) tile, K staged 32, double-buffered smem, 1 bar/stage.
// 8 warps = 4(m) x 2(n), warp 32x64.
// Stage layout in dyn smem: Ws 128x36 (4608 w) then Xs 32x136 (4352 w).
// ===========================================================================
#define CV_WS 4608
#define CV_STG 8960
#define CV_SMEM (2*CV_STG*4)

__device__ __forceinline__ void conv_load(
    const float* __restrict__ W, const float* __restrict__ Xb,
    int o0, int t0, int k0, int tid, float4 wr[4], float4 xr[4])
{
    #pragma unroll
    for (int l = 0; l < 4; l++) {
        int idx = tid + l * 256;
        int o = idx >> 3, c = (idx & 7) * 4;
        wr[l] = *(const float4*)&W[(size_t)(o0 + o) * EE + k0 + c];
    }
    #pragma unroll
    for (int l = 0; l < 4; l++) {
        int idx = tid + l * 256;
        int c = idx >> 5, t = (idx & 31) * 4;
        xr[l] = *(const float4*)&Xb[(size_t)(k0 + c) * TT + t0 + t];
    }
}

__device__ __forceinline__ void conv_store(
    unsigned* __restrict__ base, int tid, const float4 wr[4], const float4 xr[4])
{
    unsigned* Ws = base;
    unsigned* Xs = base + CV_WS;
    #pragma unroll
    for (int l = 0; l < 4; l++) {
        int idx = tid + l * 256;
        int o = idx >> 3, c = (idx & 7) * 4;
        Ws[o*36 + c+0] = f2tf(wr[l].x); Ws[o*36 + c+1] = f2tf(wr[l].y);
        Ws[o*36 + c+2] = f2tf(wr[l].z); Ws[o*36 + c+3] = f2tf(wr[l].w);
    }
    #pragma unroll
    for (int l = 0; l < 4; l++) {
        int idx = tid + l * 256;
        int c = idx >> 5, t = (idx & 31) * 4;
        Xs[c*136 + t+0] = f2tf(xr[l].x); Xs[c*136 + t+1] = f2tf(xr[l].y);
        Xs[c*136 + t+2] = f2tf(xr[l].z); Xs[c*136 + t+3] = f2tf(xr[l].w);
    }
}

__device__ __forceinline__ void gemm_conv_tf32(
    const float* __restrict__ W, const float* __restrict__ X,
    const float* __restrict__ bias, const float* __restrict__ mask,
    float* __restrict__ Y, int b)
{
    extern __shared__ unsigned sh[];
    const int tid = threadIdx.x, lane = tid & 31, warp = tid >> 5;
    const int g = lane >> 2, t4 = lane & 3;
    const int wm = warp >> 1, wn = warp & 1;
    const int o0 = blockIdx.y * 128, t0 = blockIdx.x * 128;
    const float* Xb = X + (size_t)b * EE * TT;

    float acc[2][8][4];
    #pragma unroll
    for (int i = 0; i < 2; i++)
        #pragma unroll
        for (int j = 0; j < 8; j++)
            #pragma unroll
            for (int e = 0; e < 4; e++) acc[i][j][e] = 0.f;

    float4 wr[4], xr[4];
    conv_load(W, Xb, o0, t0, 0, tid, wr, xr);
    conv_store(sh, tid, wr, xr);
    __syncthreads();

    const int NS = EE / 32;
    for (int s = 0; s < NS; s++) {
        unsigned* base = sh + (s & 1) * CV_STG;
        if (s + 1 < NS) conv_load(W, Xb, o0, t0, (s + 1) * 32, tid, wr, xr);

        const unsigned* Ws = base;
        const unsigned* Xs = base + CV_WS;
        #pragma unroll
        for (int kk = 0; kk < 32; kk += 8) {
            unsigned a[2][4], bf[8][2];
            #pragma unroll
            for (int mt = 0; mt < 2; mt++) {
                int m = wm * 32 + mt * 16;
                a[mt][0] = Ws[(m + g    )*36 + kk + t4];
                a[mt][1] = Ws[(m + g + 8)*36 + kk + t4];
                a[mt][2] = Ws[(m + g    )*36 + kk + t4 + 4];
                a[mt][3] = Ws[(m + g + 8)*36 + kk + t4 + 4];
            }
            #pragma unroll
            for (int nt = 0; nt < 8; nt++) {
                int n = wn * 64 + nt * 8 + g;
                bf[nt][0] = Xs[(kk + t4    )*136 + n];
                bf[nt][1] = Xs[(kk + t4 + 4)*136 + n];
            }
            #pragma unroll
            for (int mt = 0; mt < 2; mt++)
                #pragma unroll
                for (int nt = 0; nt < 8; nt++)
                    mma8(acc[mt][nt], a[mt], bf[nt]);
        }

        if (s + 1 < NS)
            conv_store(sh + ((s + 1) & 1) * CV_STG, tid, wr, xr);
        __syncthreads();
    }

    #pragma unroll
    for (int mt = 0; mt < 2; mt++) {
        int o_lo = o0 + wm * 32 + mt * 16 + g;
        float b_lo = bias[o_lo], b_hi = bias[o_lo + 8];
        #pragma unroll
        for (int nt = 0; nt < 8; nt++) {
            int t = t0 + wn * 64 + nt * 8 + 2 * t4;
            float mk0 = mask[(size_t)b * TT + t];
            float mk1 = mask[(size_t)b * TT + t + 1];
            float2 v0 = make_float2(mk0 * acc[mt][nt][0] + b_lo,
                                    mk1 * acc[mt][nt][1] + b_lo);
            float2 v1 = make_float2(mk0 * acc[mt][nt][2] + b_hi,
                                    mk1 * acc[mt][nt][3] + b_hi);
            *(float2*)&Y[(size_t)b * EE * TT + (size_t)o_lo * TT + t]       = v0;
            *(float2*)&Y[(size_t)b * EE * TT + (size_t)(o_lo + 8) * TT + t] = v1;
        }
    }
}

__global__ void __launch_bounds__(256)
conv3_kernel(const float* __restrict__ q, const float* __restrict__ k,
             const float* __restrict__ v,
             const float* __restrict__ qm, const float* __restrict__ km,
             const float* __restrict__ vm,
             const float* __restrict__ Wq, const float* __restrict__ bq,
             const float* __restrict__ Wk, const float* __restrict__ bk,
             const float* __restrict__ Wv, const float* __restrict__ bv)
{
    int m = blockIdx.z >> 1;
    int b = blockIdx.z & 1;
    if (m == 0)      gemm_conv_tf32(Wq, q, bq, qm, g_qp, b);
    else if (m == 1) gemm_conv_tf32(Wk, k, bk, km, g_kp, b);
    else             gemm_conv_tf32(Wv, v, bv, vm, g_vp, b);
}

__global__ void __launch_bounds__(256)
conv_final_kernel(const float* __restrict__ Wo, const float* __restrict__ bo,
                  const float* __restrict__ km, float* __restrict__ out)
{
    gemm_conv_tf32(Wo, g_o, bo, km, out, blockIdx.z);
}

// ===========================================================================
// Scores: per (b,h, 64 q rows). S = Q^T K (inner = 64 = DH). Single pass:
//   P[q,k] = exp(s*qm*km*scale) * km  (unnormalized); l_q accumulated.
// Ks double-buffered in dyn smem (2 x 64x72 words). Q tile static, frags in regs.
// 8 warps = 4(m:q) x 2(n:k); k chunks of 64.
// ===========================================================================
#define SC_STG 4608
#define SC_SMEM (2*SC_STG*4)

__device__ __forceinline__ void sc_kload(
    const float* __restrict__ K, int kc, int tid, float4 kr[4])
{
    #pragma unroll
    for (int l = 0; l < 4; l++) {
        int idx = tid + l * 256;
        int d = idx >> 4, k4 = (idx & 15) * 4;
        kr[l] = *(const float4*)&K[(size_t)d * TT + kc + k4];
    }
}

__device__ __forceinline__ void sc_kstore(unsigned* __restrict__ Ks, int tid, const float4 kr[4])
{
    #pragma unroll
    for (int l = 0; l < 4; l++) {
        int idx = tid + l * 256;
        int d = idx >> 4, k4 = (idx & 15) * 4;
        Ks[d*72 + k4+0] = f2tf(kr[l].x); Ks[d*72 + k4+1] = f2tf(kr[l].y);
        Ks[d*72 + k4+2] = f2tf(kr[l].z); Ks[d*72 + k4+3] = f2tf(kr[l].w);
    }
}

__global__ void __launch_bounds__(256)
scores_tf32(const float* __restrict__ qmask, const float* __restrict__ kmask)
{
    extern __shared__ unsigned sh[];
    __shared__ unsigned Qs[64][68];   // [m=q][k=d]
    __shared__ float lw[4][2][16];

    const int b = blockIdx.z, h = blockIdx.y, q0 = blockIdx.x * 64;
    const float* Q = g_qp + ((size_t)b * EE + h * DHH) * TT;
    const float* K = g_kp + ((size_t)b * EE + h * DHH) * TT;
    float* P = g_att + (size_t)(b * HH + h) * TT * TT;

    const int tid = threadIdx.x, lane = tid & 31, warp = tid >> 5;
    const int g = lane >> 2, t4 = lane & 3;
    const int wm = warp >> 1, wn = warp & 1;
    const int wq = wm * 16;

    // stage Q tile transposed: Qs[q][d]
    #pragma unroll
    for (int l = 0; l < 4; l++) {
        int idx = tid + l * 256;
        int d = idx >> 4, q4 = (idx & 15) * 4;
        float4 v = *(const float4*)&Q[(size_t)d * TT + q0 + q4];
        Qs[q4+0][d] = f2tf(v.x); Qs[q4+1][d] = f2tf(v.y);
        Qs[q4+2][d] = f2tf(v.z); Qs[q4+3][d] = f2tf(v.w);
    }
    // prologue K chunk 0
    float4 kr[4];
    sc_kload(K, 0, tid, kr);
    sc_kstore(sh, tid, kr);
    __syncthreads();

    // Q fragments resident in regs for all 8 k-steps
    unsigned areg[8][4];
    #pragma unroll
    for (int ks = 0; ks < 8; ks++) {
        areg[ks][0] = Qs[wq + g    ][ks * 8 + t4];
        areg[ks][1] = Qs[wq + g + 8][ks * 8 + t4];
        areg[ks][2] = Qs[wq + g    ][ks * 8 + t4 + 4];
        areg[ks][3] = Qs[wq + g + 8][ks * 8 + t4 + 4];
    }

    const float qm0 = qmask[(size_t)b * TT + q0 + wq + g];
    const float qm1 = qmask[(size_t)b * TT + q0 + wq + g + 8];
    float l0 = 0.f, l1 = 0.f;

    const int NS = TT / 64;
    for (int s = 0; s < NS; s++) {
        const unsigned* Ks = sh + (s & 1) * SC_STG;
        if (s + 1 < NS) sc_kload(K, (s + 1) * 64, tid, kr);

        float sc[4][4];
        #pragma unroll
        for (int nt = 0; nt < 4; nt++)
            #pragma unroll
            for (int e = 0; e < 4; e++) sc[nt][e] = 0.f;

        #pragma unroll
        for (int ks = 0; ks < 8; ks++) {
            #pragma unroll
            for (int nt = 0; nt < 4; nt++) {
                unsigned bf[2];
                int n = wn * 32 + nt * 8 + g;
                bf[0] = Ks[(ks * 8 + t4    )*72 + n];
                bf[1] = Ks[(ks * 8 + t4 + 4)*72 + n];
                mma8(sc[nt], areg[ks], bf);
            }
        }

        const int kc = s * 64;
        #pragma unroll
        for (int nt = 0; nt < 4; nt++) {
            int kcol = wn * 32 + nt * 8 + 2 * t4;
            float km0 = kmask[(size_t)b * TT + kc + kcol];
            float km1 = kmask[(size_t)b * TT + kc + kcol + 1];
            float e00 = __expf(sc[nt][0] * (qm0 * km0 * SCALE));
            float e01 = __expf(sc[nt][1] * (qm0 * km1 * SCALE));
            float e10 = __expf(sc[nt][2] * (qm1 * km0 * SCALE));
            float e11 = __expf(sc[nt][3] * (qm1 * km1 * SCALE));
            l0 += e00 + e01;
            l1 += e10 + e11;
            size_t r0 = (size_t)(q0 + wq + g) * TT + kc + kcol;
            size_t r1 = (size_t)(q0 + wq + g + 8) * TT + kc + kcol;
            *(float2*)&P[r0] = make_float2(e00 * km0, e01 * km1);
            *(float2*)&P[r1] = make_float2(e10 * km0, e11 * km1);
        }

        if (s + 1 < NS) sc_kstore(sh + ((s + 1) & 1) * SC_STG, tid, kr);
        __syncthreads();
    }

    l0 += __shfl_xor_sync(0xffffffffu, l0, 1);
    l0 += __shfl_xor_sync(0xffffffffu, l0, 2);
    l1 += __shfl_xor_sync(0xffffffffu, l1, 1);
    l1 += __shfl_xor_sync(0xffffffffu, l1, 2);
    if (t4 == 0) { lw[wm][wn][g] = l0; lw[wm][wn][g + 8] = l1; }
    __syncthreads();
    if (tid < 64) {
        float l = lw[tid >> 4][0][tid & 15] + lw[tid >> 4][1][tid & 15];
        g_rl[(size_t)(b * HH + h) * TT + q0 + tid] = 1.0f / l;
    }
}

// ===========================================================================
// AV: O[d,k] = sum_q (V[d,q]*rl_q) * P[q,k].  64(d) x 128(k) tile, q staged 32,
// double-buffered. 8 warps = 2(m) x 4(n).
// Stage layout: Vs 64x36 (2304 w) then Ps 32x136 (4352 w).
// ===========================================================================
#define AV_VS 2304
#define AV_STG 6656
#define AV_SMEM (2*AV_STG*4)

__device__ __forceinline__ void av_load(
    const float* __restrict__ V, const float* __restrict__ P,
    const float* __restrict__ RL, int k0, int qc, int tid,
    float4 vr[2], float4 rr[2], float4 pr[4])
{
    #pragma unroll
    for (int l = 0; l < 2; l++) {
        int idx = tid + l * 256;
        int d = idx >> 3, q4 = (idx & 7) * 4;
        vr[l] = *(const float4*)&V[(size_t)d * TT + qc + q4];
        rr[l] = *(const float4*)&RL[qc + q4];
    }
    #pragma unroll
    for (int l = 0; l < 4; l++) {
        int idx = tid + l * 256;
        int qq = idx >> 5, k4 = (idx & 31) * 4;
        pr[l] = *(const float4*)&P[(size_t)(qc + qq) * TT + k0 + k4];
    }
}

__device__ __forceinline__ void av_store(
    unsigned* __restrict__ base, int tid,
    const float4 vr[2], const float4 rr[2], const float4 pr[4])
{
    unsigned* Vs = base;
    unsigned* Ps = base + AV_VS;
    #pragma unroll
    for (int l = 0; l < 2; l++) {
        int idx = tid + l * 256;
        int d = idx >> 3, q4 = (idx & 7) * 4;
        Vs[d*36 + q4+0] = f2tf(vr[l].x * rr[l].x);
        Vs[d*36 + q4+1] = f2tf(vr[l].y * rr[l].y);
        Vs[d*36 + q4+2] = f2tf(vr[l].z * rr[l].z);
        Vs[d*36 + q4+3] = f2tf(vr[l].w * rr[l].w);
    }
    #pragma unroll
    for (int l = 0; l < 4; l++) {
        int idx = tid + l * 256;
        int qq = idx >> 5, k4 = (idx & 31) * 4;
        Ps[qq*136 + k4+0] = f2tf(pr[l].x); Ps[qq*136 + k4+1] = f2tf(pr[l].y);
        Ps[qq*136 + k4+2] = f2tf(pr[l].z); Ps[qq*136 + k4+3] = f2tf(pr[l].w);
    }
}

__global__ void __launch_bounds__(256)
av_tf32()
{
    extern __shared__ unsigned sh[];
    const int b = blockIdx.z, h = blockIdx.y, k0 = blockIdx.x * 128;
    const float* V  = g_vp  + ((size_t)b * EE + h * DHH) * TT;
    const float* P  = g_att + (size_t)(b * HH + h) * TT * TT;
    const float* RL = g_rl  + (size_t)(b * HH + h) * TT;
    float* O = g_o + ((size_t)b * EE + h * DHH) * TT;

    const int tid = threadIdx.x, lane = tid & 31, warp = tid >> 5;
    const int g = lane >> 2, t4 = lane & 3;
    const int wm = warp >> 2, wn = warp & 3;

    float acc[2][4][4];
    #pragma unroll
    for (int i = 0; i < 2; i++)
        #pragma unroll
        for (int j = 0; j < 4; j++)
            #pragma unroll
            for (int e = 0; e < 4; e++) acc[i][j][e] = 0.f;

    float4 vr[2], rr[2], pr[4];
    av_load(V, P, RL, k0, 0, tid, vr, rr, pr);
    av_store(sh, tid, vr, rr, pr);
    __syncthreads();

    const int NS = TT / 32;
    for (int s = 0; s < NS; s++) {
        unsigned* base = sh + (s & 1) * AV_STG;
        if (s + 1 < NS) av_load(V, P, RL, k0, (s + 1) * 32, tid, vr, rr, pr);

        const unsigned* Vs = base;
        const unsigned* Ps = base + AV_VS;
        #pragma unroll
        for (int ks = 0; ks < 4; ks++) {
            unsigned a[2][4], bf[4][2];
            #pragma unroll
            for (int mt = 0; mt < 2; mt++) {
                int m = wm * 32 + mt * 16;
                a[mt][0] = Vs[(m + g    )*36 + ks * 8 + t4];
                a[mt][1] = Vs[(m + g + 8)*36 + ks * 8 + t4];
                a[mt][2] = Vs[(m + g    )*36 + ks * 8 + t4 + 4];
                a[mt][3] = Vs[(m + g + 8)*36 + ks * 8 + t4 + 4];
            }
            #pragma unroll
            for (int nt = 0; nt < 4; nt++) {
                int n = wn * 32 + nt * 8 + g;
                bf[nt][0] = Ps[(ks * 8 + t4    )*136 + n];
                bf[nt][1] = Ps[(ks * 8 + t4 + 4)*136 + n];
            }
            #pragma unroll
            for (int mt = 0; mt < 2; mt++)
                #pragma unroll
                for (int nt = 0; nt < 4; nt++)
                    mma8(acc[mt][nt], a[mt], bf[nt]);
        }

        if (s + 1 < NS) av_store(sh + ((s + 1) & 1) * AV_STG, tid, vr, rr, pr);
        __syncthreads();
    }

    #pragma unroll
    for (int mt = 0; mt < 2; mt++) {
        int d = wm * 32 + mt * 16 + g;
        #pragma unroll
        for (int nt = 0; nt < 4; nt++) {
            int kcol = k0 + wn * 32 + nt * 8 + 2 * t4;
            *(float2*)&O[(size_t)d * TT + kcol] =
                make_float2(acc[mt][nt][0], acc[mt][nt][1]);
            *(float2*)&O[(size_t)(d + 8) * TT + kcol] =
                make_float2(acc[mt][nt][2], acc[mt][nt][3]);
        }
    }
}

// ===========================================================================
extern "C" void kernel_launch(void* const* d_in, const int* in_sizes, int n_in,
                              void* d_out, int out_size)
{
    const float* q   = (const float*)d_in[0];
    const float* k   = (const float*)d_in[1];
    const float* v   = (const float*)d_in[2];
    const float* qm  = (const float*)d_in[3];
    const float* km  = (const float*)d_in[4];
    const float* vm  = (const float*)d_in[5];
    const float* Wq  = (const float*)d_in[6];
    const float* bq  = (const float*)d_in[7];
    const float* Wk  = (const float*)d_in[8];
    const float* bk  = (const float*)d_in[9];
    const float* Wv  = (const float*)d_in[10];
    const float* bv  = (const float*)d_in[11];
    const float* Wo  = (const float*)d_in[12];
    const float* bo  = (const float*)d_in[13];
    float* out = (float*)d_out;

    cudaFuncSetAttribute(conv3_kernel,      cudaFuncAttributeMaxDynamicSharedMemorySize, CV_SMEM);
    cudaFuncSetAttribute(conv_final_kernel, cudaFuncAttributeMaxDynamicSharedMemorySize, CV_SMEM);
    cudaFuncSetAttribute(scores_tf32,       cudaFuncAttributeMaxDynamicSharedMemorySize, SC_SMEM);
    cudaFuncSetAttribute(av_tf32,           cudaFuncAttributeMaxDynamicSharedMemorySize, AV_SMEM);

    dim3 g1(TT / 128, EE / 128, 3 * BB);
    conv3_kernel<<<g1, 256, CV_SMEM>>>(q, k, v, qm, km, vm, Wq, bq, Wk, bk, Wv, bv);

    dim3 g2(TT / 64, HH, BB);
    scores_tf32<<<g2, 256, SC_SMEM>>>(qm, km);

    dim3 g3(TT / 128, HH, BB);
    av_tf32<<<g3, 256, AV_SMEM>>>();

    dim3 g4(TT / 128, EE / 128, BB);
    conv_final_kernel<<<g4, 256, CV_SMEM>>>(Wo, bo, km, out);
}

// round 4
// speedup vs baseline: 5.3380x; 1.5548x over previous
#include <cuda_runtime.h>
#include <cuda_fp16.h>

#define BB 2
#define EE 1024
#define TT 2048
#define HH 16
#define DHH 64
#define SCALE 0.03125f

// Scratch (static device arrays: allocation-free rule)
__device__ float  g_qp[BB*EE*TT];                  // 16 MB
__device__ float  g_kp[BB*EE*TT];                  // 16 MB
__device__ float  g_vp[BB*EE*TT];                  // 16 MB
__device__ float  g_o [BB*EE*TT];                  // 16 MB
__device__ __half g_att_h[(size_t)BB*HH*TT*TT];    // 256 MB (unnormalized exp(s)*km, fp16)
__device__ float  g_rl [BB*HH*TT];                 // 1/l per (b,h,q)

// ---------------------------------------------------------------------------
__device__ __forceinline__ unsigned pack2(float a, float b){
    __half2 h = __floats2half2_rn(a, b);
    return *reinterpret_cast<unsigned*>(&h);
}
__device__ __forceinline__ unsigned smaddr(const void* p){
    return (unsigned)__cvta_generic_to_shared(p);
}
__device__ __forceinline__ void ldsm4(unsigned r[4], unsigned addr){
    asm volatile("ldmatrix.sync.aligned.m8n8.x4.shared.b16 {%0,%1,%2,%3}, [%4];"
        : "=r"(r[0]),"=r"(r[1]),"=r"(r[2]),"=r"(r[3]) : "r"(addr));
}
__device__ __forceinline__ void ldsm4t(unsigned r[4], unsigned addr){
    asm volatile("ldmatrix.sync.aligned.m8n8.x4.trans.shared.b16 {%0,%1,%2,%3}, [%4];"
        : "=r"(r[0]),"=r"(r[1]),"=r"(r[2]),"=r"(r[3]) : "r"(addr));
}
__device__ __forceinline__ void mma16(float c[4], const unsigned a[4], const unsigned b[2]){
    asm volatile("mma.sync.aligned.m16n8k16.row.col.f32.f16.f16.f32 "
        "{%0,%1,%2,%3},{%4,%5,%6,%7},{%8,%9},{%0,%1,%2,%3};"
        : "+f"(c[0]),"+f"(c[1]),"+f"(c[2]),"+f"(c[3])
        : "r"(a[0]),"r"(a[1]),"r"(a[2]),"r"(a[3]),"r"(b[0]),"r"(b[1]));
}

// ===========================================================================
// conv1x1: Y[b,o,t] = mask[b,t]*sum_c W[o,c]X[b,c,t] + bias[o]
// 128(o) x 128(t) tile, K staged 32, double-buffered, fp16 MMA m16n8k16.
// 8 warps = 4(m) x 2(n). Smem stage: Ws[128][40]h (A,[m][k]) Xs[32][136]h (B,[k][n]).
// ===========================================================================
#define CV_WP   40          // Ws pitch (halves): 80B = 5x16B (odd -> LDSM conflict-free)
#define CV_XP   136         // Xs pitch: 272B = 17x16B
#define CV_WS_H (128*CV_WP) // 5120
#define CV_STG_H (CV_WS_H + 32*CV_XP)  // 9472 halves
#define CV_SMEM (2*CV_STG_H*2)

__device__ __forceinline__ void conv_load(
    const float* __restrict__ W, const float* __restrict__ Xb,
    int o0, int t0, int k0, int tid, float4 wr[4], float4 xr[4])
{
    #pragma unroll
    for (int l = 0; l < 4; l++) {
        int idx = tid + l * 256;
        int o = idx >> 3, c = (idx & 7) * 4;
        wr[l] = *(const float4*)&W[(size_t)(o0 + o) * EE + k0 + c];
    }
    #pragma unroll
    for (int l = 0; l < 4; l++) {
        int idx = tid + l * 256;
        int c = idx >> 5, t = (idx & 31) * 4;
        xr[l] = *(const float4*)&Xb[(size_t)(k0 + c) * TT + t0 + t];
    }
}

__device__ __forceinline__ void conv_store(
    __half* __restrict__ base, int tid, const float4 wr[4], const float4 xr[4])
{
    __half* Ws = base;
    __half* Xs = base + CV_WS_H;
    #pragma unroll
    for (int l = 0; l < 4; l++) {
        int idx = tid + l * 256;
        int o = idx >> 3, c = (idx & 7) * 4;
        uint2 u = make_uint2(pack2(wr[l].x, wr[l].y), pack2(wr[l].z, wr[l].w));
        *(uint2*)&Ws[o*CV_WP + c] = u;
    }
    #pragma unroll
    for (int l = 0; l < 4; l++) {
        int idx = tid + l * 256;
        int c = idx >> 5, t = (idx & 31) * 4;
        uint2 u = make_uint2(pack2(xr[l].x, xr[l].y), pack2(xr[l].z, xr[l].w));
        *(uint2*)&Xs[c*CV_XP + t] = u;
    }
}

__device__ __forceinline__ void gemm_conv_h(
    const float* __restrict__ W, const float* __restrict__ X,
    const float* __restrict__ bias, const float* __restrict__ mask,
    float* __restrict__ Y, int b)
{
    extern __shared__ __half sh[];
    const int tid = threadIdx.x, lane = tid & 31, warp = tid >> 5;
    const int g = lane >> 2, t4 = lane & 3;
    const int wm = warp >> 1, wn = warp & 1;
    const int l15 = lane & 15, lhi = (lane >> 4) * 8;
    const int o0 = blockIdx.y * 128, t0 = blockIdx.x * 128;
    const float* Xb = X + (size_t)b * EE * TT;

    float acc[2][8][4];
    #pragma unroll
    for (int i = 0; i < 2; i++)
        #pragma unroll
        for (int j = 0; j < 8; j++)
            #pragma unroll
            for (int e = 0; e < 4; e++) acc[i][j][e] = 0.f;

    float4 wr[4], xr[4];
    conv_load(W, Xb, o0, t0, 0, tid, wr, xr);
    conv_store(sh, tid, wr, xr);
    __syncthreads();

    const int NS = EE / 32;
    for (int s = 0; s < NS; s++) {
        __half* base = sh + (s & 1) * CV_STG_H;
        if (s + 1 < NS) conv_load(W, Xb, o0, t0, (s + 1) * 32, tid, wr, xr);

        const unsigned wsa = smaddr(base);
        const unsigned xsa = smaddr(base + CV_WS_H);
        #pragma unroll
        for (int kk = 0; kk < 32; kk += 16) {
            unsigned a[2][4], bf[8][2];
            #pragma unroll
            for (int mt = 0; mt < 2; mt++) {
                int m = wm * 32 + mt * 16 + l15;
                ldsm4(a[mt], wsa + (m*CV_WP + kk + lhi) * 2);
            }
            #pragma unroll
            for (int nb = 0; nb < 4; nb++) {
                unsigned r[4];
                int n = wn * 64 + nb * 16 + lhi;
                ldsm4t(r, xsa + ((kk + l15)*CV_XP + n) * 2);
                bf[2*nb][0] = r[0]; bf[2*nb][1] = r[1];
                bf[2*nb+1][0] = r[2]; bf[2*nb+1][1] = r[3];
            }
            #pragma unroll
            for (int mt = 0; mt < 2; mt++)
                #pragma unroll
                for (int nt = 0; nt < 8; nt++)
                    mma16(acc[mt][nt], a[mt], bf[nt]);
        }

        if (s + 1 < NS)
            conv_store(sh + ((s + 1) & 1) * CV_STG_H, tid, wr, xr);
        __syncthreads();
    }

    #pragma unroll
    for (int mt = 0; mt < 2; mt++) {
        int o_lo = o0 + wm * 32 + mt * 16 + g;
        float b_lo = bias[o_lo], b_hi = bias[o_lo + 8];
        #pragma unroll
        for (int nt = 0; nt < 8; nt++) {
            int t = t0 + wn * 64 + nt * 8 + 2 * t4;
            float mk0 = mask[(size_t)b * TT + t];
            float mk1 = mask[(size_t)b * TT + t + 1];
            float2 v0 = make_float2(mk0 * acc[mt][nt][0] + b_lo,
                                    mk1 * acc[mt][nt][1] + b_lo);
            float2 v1 = make_float2(mk0 * acc[mt][nt][2] + b_hi,
                                    mk1 * acc[mt][nt][3] + b_hi);
            *(float2*)&Y[(size_t)b * EE * TT + (size_t)o_lo * TT + t]       = v0;
            *(float2*)&Y[(size_t)b * EE * TT + (size_t)(o_lo + 8) * TT + t] = v1;
        }
    }
}

__global__ void __launch_bounds__(256)
conv3_kernel(const float* __restrict__ q, const float* __restrict__ k,
             const float* __restrict__ v,
             const float* __restrict__ qm, const float* __restrict__ km,
             const float* __restrict__ vm,
             const float* __restrict__ Wq, const float* __restrict__ bq,
             const float* __restrict__ Wk, const float* __restrict__ bk,
             const float* __restrict__ Wv, const float* __restrict__ bv)
{
    int m = blockIdx.z >> 1;
    int b = blockIdx.z & 1;
    if (m == 0)      gemm_conv_h(Wq, q, bq, qm, g_qp, b);
    else if (m == 1) gemm_conv_h(Wk, k, bk, km, g_kp, b);
    else             gemm_conv_h(Wv, v, bv, vm, g_vp, b);
}

__global__ void __launch_bounds__(256)
conv_final_kernel(const float* __restrict__ Wo, const float* __restrict__ bo,
                  const float* __restrict__ km, float* __restrict__ out)
{
    gemm_conv_h(Wo, g_o, bo, km, out, blockIdx.z);
}

// ===========================================================================
// Scores: per (b,h, 64 q rows). P[q,k] = exp(s*qm*km*scale)*km (fp16, unnorm).
// Q tile static smem [q][d] (A frags preloaded); Ks double-buffered [d][kcol].
// 8 warps = 4(m:q) x 2(n:k); k chunks of 64; fp16 MMA.
// ===========================================================================
#define SC_QP 72
#define SC_KP 72
#define SC_STG_H (64*SC_KP)      // 4608 halves
#define SC_SMEM (2*SC_STG_H*2)

__device__ __forceinline__ void sc_kload(
    const float* __restrict__ K, int kc, int tid, float4 kr[4])
{
    #pragma unroll
    for (int l = 0; l < 4; l++) {
        int idx = tid + l * 256;
        int d = idx >> 4, k4 = (idx & 15) * 4;
        kr[l] = *(const float4*)&K[(size_t)d * TT + kc + k4];
    }
}

__device__ __forceinline__ void sc_kstore(__half* __restrict__ Ks, int tid, const float4 kr[4])
{
    #pragma unroll
    for (int l = 0; l < 4; l++) {
        int idx = tid + l * 256;
        int d = idx >> 4, k4 = (idx & 15) * 4;
        uint2 u = make_uint2(pack2(kr[l].x, kr[l].y), pack2(kr[l].z, kr[l].w));
        *(uint2*)&Ks[d*SC_KP + k4] = u;
    }
}

__global__ void __launch_bounds__(256)
scores_h(const float* __restrict__ qmask, const float* __restrict__ kmask)
{
    extern __shared__ __half sh[];
    __shared__ __half Qs[64*SC_QP];   // [q][d]
    __shared__ float lw[4][2][16];

    const int b = blockIdx.z, h = blockIdx.y, q0 = blockIdx.x * 64;
    const float* Q = g_qp + ((size_t)b * EE + h * DHH) * TT;
    const float* K = g_kp + ((size_t)b * EE + h * DHH) * TT;
    __half* P = g_att_h + (size_t)(b * HH + h) * TT * TT;

    const int tid = threadIdx.x, lane = tid & 31, warp = tid >> 5;
    const int g = lane >> 2, t4 = lane & 3;
    const int wm = warp >> 1, wn = warp & 1;
    const int l15 = lane & 15, lhi = (lane >> 4) * 8;
    const int wq = wm * 16;

    // stage Q tile transposed: Qs[q][d]
    #pragma unroll
    for (int l = 0; l < 4; l++) {
        int idx = tid + l * 256;
        int d = idx >> 4, q4 = (idx & 15) * 4;
        float4 v = *(const float4*)&Q[(size_t)d * TT + q0 + q4];
        Qs[(q4+0)*SC_QP + d] = __float2half_rn(v.x);
        Qs[(q4+1)*SC_QP + d] = __float2half_rn(v.y);
        Qs[(q4+2)*SC_QP + d] = __float2half_rn(v.z);
        Qs[(q4+3)*SC_QP + d] = __float2half_rn(v.w);
    }
    float4 kr[4];
    sc_kload(K, 0, tid, kr);
    sc_kstore(sh, tid, kr);
    __syncthreads();

    // Q fragments resident for 4 ksteps (d = 0..63 by 16)
    unsigned areg[4][4];
    const unsigned qsa = smaddr(Qs);
    #pragma unroll
    for (int ks = 0; ks < 4; ks++)
        ldsm4(areg[ks], qsa + ((wq + l15)*SC_QP + ks*16 + lhi) * 2);

    const float qm0 = qmask[(size_t)b * TT + q0 + wq + g];
    const float qm1 = qmask[(size_t)b * TT + q0 + wq + g + 8];
    float l0 = 0.f, l1 = 0.f;

    const int NS = TT / 64;
    for (int s = 0; s < NS; s++) {
        const unsigned ksa = smaddr(sh + (s & 1) * SC_STG_H);
        if (s + 1 < NS) sc_kload(K, (s + 1) * 64, tid, kr);

        float sc[4][4];
        #pragma unroll
        for (int nt = 0; nt < 4; nt++)
            #pragma unroll
            for (int e = 0; e < 4; e++) sc[nt][e] = 0.f;

        #pragma unroll
        for (int ks = 0; ks < 4; ks++) {
            unsigned bf[4][2];
            #pragma unroll
            for (int nb = 0; nb < 2; nb++) {
                unsigned r[4];
                int n = wn * 32 + nb * 16 + lhi;
                ldsm4t(r, ksa + ((ks*16 + l15)*SC_KP + n) * 2);
                bf[2*nb][0] = r[0]; bf[2*nb][1] = r[1];
                bf[2*nb+1][0] = r[2]; bf[2*nb+1][1] = r[3];
            }
            #pragma unroll
            for (int nt = 0; nt < 4; nt++)
                mma16(sc[nt], areg[ks], bf[nt]);
        }

        const int kc = s * 64;
        #pragma unroll
        for (int nt = 0; nt < 4; nt++) {
            int kcol = wn * 32 + nt * 8 + 2 * t4;
            float km0 = kmask[(size_t)b * TT + kc + kcol];
            float km1 = kmask[(size_t)b * TT + kc + kcol + 1];
            float e00 = __expf(sc[nt][0] * (qm0 * km0 * SCALE));
            float e01 = __expf(sc[nt][1] * (qm0 * km1 * SCALE));
            float e10 = __expf(sc[nt][2] * (qm1 * km0 * SCALE));
            float e11 = __expf(sc[nt][3] * (qm1 * km1 * SCALE));
            l0 += e00 + e01;
            l1 += e10 + e11;
            size_t r0 = (size_t)(q0 + wq + g) * TT + kc + kcol;
            size_t r1 = (size_t)(q0 + wq + g + 8) * TT + kc + kcol;
            *(unsigned*)&P[r0] = pack2(e00 * km0, e01 * km1);
            *(unsigned*)&P[r1] = pack2(e10 * km0, e11 * km1);
        }

        if (s + 1 < NS) sc_kstore(sh + ((s + 1) & 1) * SC_STG_H, tid, kr);
        __syncthreads();
    }

    l0 += __shfl_xor_sync(0xffffffffu, l0, 1);
    l0 += __shfl_xor_sync(0xffffffffu, l0, 2);
    l1 += __shfl_xor_sync(0xffffffffu, l1, 1);
    l1 += __shfl_xor_sync(0xffffffffu, l1, 2);
    if (t4 == 0) { lw[wm][wn][g] = l0; lw[wm][wn][g + 8] = l1; }
    __syncthreads();
    if (tid < 64) {
        float l = lw[tid >> 4][0][tid & 15] + lw[tid >> 4][1][tid & 15];
        g_rl[(size_t)(b * HH + h) * TT + q0 + tid] = 1.0f / l;
    }
}

// ===========================================================================
// AV: O[d,k] = sum_q (V[d,q]*rl_q) * P[q,k]. 64(d) x 128(k), q staged 32,
// double-buffered, fp16 MMA. P already fp16 in gmem (no cvt on load).
// 8 warps = 2(m) x 4(n). Stage: Vs[64][40]h, Ps[32][136]h.
// ===========================================================================
#define AV_VP 40
#define AV_PP 136
#define AV_VS_H (64*AV_VP)             // 2560
#define AV_STG_H (AV_VS_H + 32*AV_PP)  // 6912 halves
#define AV_SMEM (2*AV_STG_H*2)

__device__ __forceinline__ void av_load(
    const float* __restrict__ V, const __half* __restrict__ P,
    const float* __restrict__ RL, int k0, int qc, int tid,
    float4 vr[2], float4 rr[2], uint4 pr[2])
{
    #pragma unroll
    for (int l = 0; l < 2; l++) {
        int idx = tid + l * 256;
        int d = idx >> 3, q4 = (idx & 7) * 4;
        vr[l] = *(const float4*)&V[(size_t)d * TT + qc + q4];
        rr[l] = *(const float4*)&RL[qc + q4];
    }
    #pragma unroll
    for (int l = 0; l < 2; l++) {
        int idx = tid + l * 256;              // 512 uint4 over 32q x 128k halves
        int qq = idx >> 4, hc = (idx & 15) * 8;
        pr[l] = *(const uint4*)&P[(size_t)(qc + qq) * TT + k0 + hc];
    }
}

__device__ __forceinline__ void av_store(
    __half* __restrict__ base, int tid,
    const float4 vr[2], const float4 rr[2], const uint4 pr[2])
{
    __half* Vs = base;
    __half* Ps = base + AV_VS_H;
    #pragma unroll
    for (int l = 0; l < 2; l++) {
        int idx = tid + l * 256;
        int d = idx >> 3, q4 = (idx & 7) * 4;
        uint2 u = make_uint2(pack2(vr[l].x * rr[l].x, vr[l].y * rr[l].y),
                             pack2(vr[l].z * rr[l].z, vr[l].w * rr[l].w));
        *(uint2*)&Vs[d*AV_VP + q4] = u;
    }
    #pragma unroll
    for (int l = 0; l < 2; l++) {
        int idx = tid + l * 256;
        int qq = idx >> 4, hc = (idx & 15) * 8;
        *(uint4*)&Ps[qq*AV_PP + hc] = pr[l];
    }
}

__global__ void __launch_bounds__(256)
av_h()
{
    extern __shared__ __half sh[];
    const int b = blockIdx.z, h = blockIdx.y, k0 = blockIdx.x * 128;
    const float*  V  = g_vp  + ((size_t)b * EE + h * DHH) * TT;
    const __half* P  = g_att_h + (size_t)(b * HH + h) * TT * TT;
    const float*  RL = g_rl  + (size_t)(b * HH + h) * TT;
    float* O = g_o + ((size_t)b * EE + h * DHH) * TT;

    const int tid = threadIdx.x, lane = tid & 31, warp = tid >> 5;
    const int g = lane >> 2, t4 = lane & 3;
    const int wm = warp >> 2, wn = warp & 3;
    const int l15 = lane & 15, lhi = (lane >> 4) * 8;

    float acc[2][4][4];
    #pragma unroll
    for (int i = 0; i < 2; i++)
        #pragma unroll
        for (int j = 0; j < 4; j++)
            #pragma unroll
            for (int e = 0; e < 4; e++) acc[i][j][e] = 0.f;

    float4 vr[2], rr[2];
    uint4 pr[2];
    av_load(V, P, RL, k0, 0, tid, vr, rr, pr);
    av_store(sh, tid, vr, rr, pr);
    __syncthreads();

    const int NS = TT / 32;
    for (int s = 0; s < NS; s++) {
        __half* base = sh + (s & 1) * AV_STG_H;
        if (s + 1 < NS) av_load(V, P, RL, k0, (s + 1) * 32, tid, vr, rr, pr);

        const unsigned vsa = smaddr(base);
        const unsigned psa = smaddr(base + AV_VS_H);
        #pragma unroll
        for (int ks = 0; ks < 2; ks++) {
            unsigned a[2][4], bf[4][2];
            #pragma unroll
            for (int mt = 0; mt < 2; mt++) {
                int m = wm * 32 + mt * 16 + l15;
                ldsm4(a[mt], vsa + (m*AV_VP + ks*16 + lhi) * 2);
            }
            #pragma unroll
            for (int nb = 0; nb < 2; nb++) {
                unsigned r[4];
                int n = wn * 32 + nb * 16 + lhi;
                ldsm4t(r, psa + ((ks*16 + l15)*AV_PP + n) * 2);
                bf[2*nb][0] = r[0]; bf[2*nb][1] = r[1];
                bf[2*nb+1][0] = r[2]; bf[2*nb+1][1] = r[3];
            }
            #pragma unroll
            for (int mt = 0; mt < 2; mt++)
                #pragma unroll
                for (int nt = 0; nt < 4; nt++)
                    mma16(acc[mt][nt], a[mt], bf[nt]);
        }

        if (s + 1 < NS) av_store(sh + ((s + 1) & 1) * AV_STG_H, tid, vr, rr, pr);
        __syncthreads();
    }

    #pragma unroll
    for (int mt = 0; mt < 2; mt++) {
        int d = wm * 32 + mt * 16 + g;
        #pragma unroll
        for (int nt = 0; nt < 4; nt++) {
            int kcol = k0 + wn * 32 + nt * 8 + 2 * t4;
            *(float2*)&O[(size_t)d * TT + kcol] =
                make_float2(acc[mt][nt][0], acc[mt][nt][1]);
            *(float2*)&O[(size_t)(d + 8) * TT + kcol] =
                make_float2(acc[mt][nt][2], acc[mt][nt][3]);
        }
    }
}

// ===========================================================================
extern "C" void kernel_launch(void* const* d_in, const int* in_sizes, int n_in,
                              void* d_out, int out_size)
{
    const float* q   = (const float*)d_in[0];
    const float* k   = (const float*)d_in[1];
    const float* v   = (const float*)d_in[2];
    const float* qm  = (const float*)d_in[3];
    const float* km  = (const float*)d_in[4];
    const float* vm  = (const float*)d_in[5];
    const float* Wq  = (const float*)d_in[6];
    const float* bq  = (const float*)d_in[7];
    const float* Wk  = (const float*)d_in[8];
    const float* bk  = (const float*)d_in[9];
    const float* Wv  = (const float*)d_in[10];
    const float* bv  = (const float*)d_in[11];
    const float* Wo  = (const float*)d_in[12];
    const float* bo  = (const float*)d_in[13];
    float* out = (float*)d_out;

    cudaFuncSetAttribute(conv3_kernel,      cudaFuncAttributeMaxDynamicSharedMemorySize, CV_SMEM);
    cudaFuncSetAttribute(conv_final_kernel, cudaFuncAttributeMaxDynamicSharedMemorySize, CV_SMEM);
    cudaFuncSetAttribute(scores_h,          cudaFuncAttributeMaxDynamicSharedMemorySize, SC_SMEM);
    cudaFuncSetAttribute(av_h,              cudaFuncAttributeMaxDynamicSharedMemorySize, AV_SMEM);

    dim3 g1(TT / 128, EE / 128, 3 * BB);
    conv3_kernel<<<g1, 256, CV_SMEM>>>(q, k, v, qm, km, vm, Wq, bq, Wk, bk, Wv, bv);

    dim3 g2(TT / 64, HH, BB);
    scores_h<<<g2, 256, SC_SMEM>>>(qm, km);

    dim3 g3(TT / 128, HH, BB);
    av_h<<<g3, 256, AV_SMEM>>>();

    dim3 g4(TT / 128, EE / 128, BB);
    conv_final_kernel<<<g4, 256, CV_SMEM>>>(Wo, bo, km, out);
}

// round 7
// speedup vs baseline: 6.5075x; 1.2191x over previous
#include <cuda_runtime.h>
#include <cuda_fp16.h>

#define BB 2
#define EE 1024
#define TT 2048
#define HH 16
#define DHH 64
#define SCALE 0.03125f

// ---------------------------------------------------------------------------
// fp16 scratch (static device arrays; 16B aligned for cp.async / vector ops)
// ---------------------------------------------------------------------------
__device__ __align__(16) __half g_xh[3*BB*EE*TT];              // converted q,k,v inputs
__device__ __align__(16) __half g_wh[4*EE*EE];                 // converted Wq,Wk,Wv,Wo
__device__ __align__(16) __half g_qp[BB*EE*TT];                // Q proj
__device__ __align__(16) __half g_kp[BB*EE*TT];                // K proj
__device__ __align__(16) __half g_vp[BB*EE*TT];                // V proj
__device__ __align__(16) __half g_vs[BB*EE*TT];                // V * rl
__device__ __align__(16) __half g_oh[BB*EE*TT];                // attention output O
__device__ __align__(16) __half g_att[(size_t)BB*HH*TT*TT];    // 256 MB unnorm exp(s)*km
__device__ float g_rl[BB*HH*TT];                               // 1/l per (b,h,q)

// ---------------------------------------------------------------------------
__device__ __forceinline__ unsigned smaddr(const void* p){
    return (unsigned)__cvta_generic_to_shared(p);
}
__device__ __forceinline__ void cpa16(unsigned dst, const void* src){
    asm volatile("cp.async.cg.shared.global [%0], [%1], 16;" :: "r"(dst), "l"(src));
}
__device__ __forceinline__ void cpa_commit(){
    asm volatile("cp.async.commit_group;");
}
template<int N> __device__ __forceinline__ void cpa_wait(){
    asm volatile("cp.async.wait_group %0;" :: "n"(N));
}
__device__ __forceinline__ void ldsm4(unsigned r[4], unsigned addr){
    asm volatile("ldmatrix.sync.aligned.m8n8.x4.shared.b16 {%0,%1,%2,%3}, [%4];"
        : "=r"(r[0]),"=r"(r[1]),"=r"(r[2]),"=r"(r[3]) : "r"(addr));
}
__device__ __forceinline__ void ldsm4t(unsigned r[4], unsigned addr){
    asm volatile("ldmatrix.sync.aligned.m8n8.x4.trans.shared.b16 {%0,%1,%2,%3}, [%4];"
        : "=r"(r[0]),"=r"(r[1]),"=r"(r[2]),"=r"(r[3]) : "r"(addr));
}
__device__ __forceinline__ void mma16(float c[4], const unsigned a[4], const unsigned b[2]){
    asm volatile("mma.sync.aligned.m16n8k16.row.col.f32.f16.f16.f32 "
        "{%0,%1,%2,%3},{%4,%5,%6,%7},{%8,%9},{%0,%1,%2,%3};"
        : "+f"(c[0]),"+f"(c[1]),"+f"(c[2]),"+f"(c[3])
        : "r"(a[0]),"r"(a[1]),"r"(a[2]),"r"(a[3]),"r"(b[0]),"r"(b[1]));
}

// ===========================================================================
// Converters
// ===========================================================================
__global__ void __launch_bounds__(256)
cvt_in(const float* __restrict__ q, const float* __restrict__ k,
       const float* __restrict__ v)
{
    const float* src = (blockIdx.z == 0) ? q : (blockIdx.z == 1) ? k : v;
    __half* dst = g_xh + (size_t)blockIdx.z * BB * EE * TT;
    size_t i = ((size_t)blockIdx.x * 256 + threadIdx.x) * 4;
    float4 x = *(const float4*)&src[i];
    *(__half2*)&dst[i]     = __floats2half2_rn(x.x, x.y);
    *(__half2*)&dst[i + 2] = __floats2half2_rn(x.z, x.w);
}

__global__ void __launch_bounds__(256)
cvt_w(const float* __restrict__ wq, const float* __restrict__ wk,
      const float* __restrict__ wv, const float* __restrict__ wo)
{
    const float* src = (blockIdx.z == 0) ? wq : (blockIdx.z == 1) ? wk :
                       (blockIdx.z == 2) ? wv : wo;
    __half* dst = g_wh + (size_t)blockIdx.z * EE * EE;
    size_t i = ((size_t)blockIdx.x * 256 + threadIdx.x) * 4;
    float4 x = *(const float4*)&src[i];
    *(__half2*)&dst[i]     = __floats2half2_rn(x.x, x.y);
    *(__half2*)&dst[i + 2] = __floats2half2_rn(x.z, x.w);
}

// ===========================================================================
// conv1x1 GEMM (fp16 in, fp32 acc): Y[o,t] = mask[t]*sum_c W[o,c]X[c,t] + b[o]
// 128(o)x128(t) tile, K staged 32, 4-stage cp.async. 8 warps = 4(m)x2(n).
// Stage: A[128][40]h (W, [m][k]) + B[32][136]h (X, [k][n]).
// Tail: empty commit_group per no-issue iteration keeps wait<2> sound.
// ===========================================================================
#define CV_AP 40
#define CV_BP 136
#define CV_A_H  (128*CV_AP)               // 5120
#define CV_STG_H (CV_A_H + 32*CV_BP)      // 9472 halves
#define CV_SMEM (4*CV_STG_H*2)            // 75776 B

template<bool OUT_HALF>
__device__ __forceinline__ void gemm_conv(
    const __half* __restrict__ Wh, const __half* __restrict__ Xb,
    const float* __restrict__ bias, const float* __restrict__ maskb,
    void* __restrict__ Yv, size_t y_off)
{
    extern __shared__ __half sh[];
    const int tid = threadIdx.x, lane = tid & 31, warp = tid >> 5;
    const int g = lane >> 2, t4 = lane & 3;
    const int wm = warp >> 1, wn = warp & 1;
    const int l15 = lane & 15, lhi = (lane >> 4) * 8;
    const int o0 = blockIdx.y * 128, t0 = blockIdx.x * 128;

    float acc[2][8][4];
    #pragma unroll
    for (int i = 0; i < 2; i++)
        #pragma unroll
        for (int j = 0; j < 8; j++)
            #pragma unroll
            for (int e = 0; e < 4; e++) acc[i][j][e] = 0.f;

    auto issue = [&](int s) {
        int k0 = s * 32;
        unsigned ab = smaddr(sh + (s & 3) * CV_STG_H);
        unsigned bb = ab + CV_A_H * 2;
        #pragma unroll
        for (int l = 0; l < 2; l++) {
            int idx = tid + l * 256;
            int r = idx >> 2, c8 = (idx & 3) * 8;
            cpa16(ab + (r * CV_AP + c8) * 2, Wh + (size_t)(o0 + r) * EE + k0 + c8);
        }
        #pragma unroll
        for (int l = 0; l < 2; l++) {
            int idx = tid + l * 256;
            int r = idx >> 4, c8 = (idx & 15) * 8;
            cpa16(bb + (r * CV_BP + c8) * 2, Xb + (size_t)(k0 + r) * TT + t0 + c8);
        }
        cpa_commit();
    };

    const int NS = EE / 32;   // 32
    issue(0); issue(1); issue(2);

    for (int s = 0; s < NS; s++) {
        cpa_wait<2>();
        __syncthreads();
        unsigned ab = smaddr(sh + (s & 3) * CV_STG_H);
        unsigned bb = ab + CV_A_H * 2;
        #pragma unroll
        for (int kk = 0; kk < 32; kk += 16) {
            unsigned a[2][4], bf[8][2];
            #pragma unroll
            for (int mt = 0; mt < 2; mt++)
                ldsm4(a[mt], ab + ((wm*32 + mt*16 + l15) * CV_AP + kk + lhi) * 2);
            #pragma unroll
            for (int nb = 0; nb < 4; nb++) {
                unsigned r[4];
                ldsm4t(r, bb + ((kk + l15) * CV_BP + wn*64 + nb*16 + lhi) * 2);
                bf[2*nb][0]   = r[0]; bf[2*nb][1]   = r[1];
                bf[2*nb+1][0] = r[2]; bf[2*nb+1][1] = r[3];
            }
            #pragma unroll
            for (int mt = 0; mt < 2; mt++)
                #pragma unroll
                for (int nt = 0; nt < 8; nt++)
                    mma16(acc[mt][nt], a[mt], bf[nt]);
        }
        if (s + 3 < NS) issue(s + 3);
        else            cpa_commit();      // empty group: keeps wait<2> == "group s done"
    }

    #pragma unroll
    for (int mt = 0; mt < 2; mt++) {
        int o_lo = o0 + wm * 32 + mt * 16 + g;
        float b_lo = bias[o_lo], b_hi = bias[o_lo + 8];
        #pragma unroll
        for (int nt = 0; nt < 8; nt++) {
            int t = t0 + wn * 64 + nt * 8 + 2 * t4;
            float mk0 = maskb[t], mk1 = maskb[t + 1];
            float y00 = mk0 * acc[mt][nt][0] + b_lo;
            float y01 = mk1 * acc[mt][nt][1] + b_lo;
            float y10 = mk0 * acc[mt][nt][2] + b_hi;
            float y11 = mk1 * acc[mt][nt][3] + b_hi;
            if (OUT_HALF) {
                __half* Y = (__half*)Yv + y_off;
                *(__half2*)&Y[(size_t)o_lo * TT + t]       = __floats2half2_rn(y00, y01);
                *(__half2*)&Y[(size_t)(o_lo + 8) * TT + t] = __floats2half2_rn(y10, y11);
            } else {
                float* Y = (float*)Yv + y_off;
                *(float2*)&Y[(size_t)o_lo * TT + t]       = make_float2(y00, y01);
                *(float2*)&Y[(size_t)(o_lo + 8) * TT + t] = make_float2(y10, y11);
            }
        }
    }
}

__global__ void __launch_bounds__(256)
conv3_kernel(const float* __restrict__ qm, const float* __restrict__ km,
             const float* __restrict__ vm,
             const float* __restrict__ bq, const float* __restrict__ bk,
             const float* __restrict__ bv)
{
    int m = blockIdx.z >> 1;
    int b = blockIdx.z & 1;
    const __half* Wh = g_wh + (size_t)m * EE * EE;
    const __half* Xb = g_xh + ((size_t)m * BB + b) * EE * TT;
    size_t yoff = (size_t)b * EE * TT;
    const float* mask = ((m == 0) ? qm : (m == 1) ? km : vm) + (size_t)b * TT;
    const float* bias = (m == 0) ? bq : (m == 1) ? bk : bv;
    __half* Y = (m == 0) ? g_qp : (m == 1) ? g_kp : g_vp;
    gemm_conv<true>(Wh, Xb, bias, mask, Y, yoff);
}

__global__ void __launch_bounds__(256)
conv_final_kernel(const float* __restrict__ bo, const float* __restrict__ km,
                  float* __restrict__ out)
{
    int b = blockIdx.z;
    gemm_conv<false>(g_wh + (size_t)3 * EE * EE,
                     g_oh + (size_t)b * EE * TT,
                     bo, km + (size_t)b * TT, out, (size_t)b * EE * TT);
}

// ===========================================================================
// Scores: per (b,h, 64 q rows). P[q,k] = exp(s*qm*km*scale)*km (fp16, unnorm),
// l_q accumulated -> g_rl. Q tile scalar-transposed into [q][d] smem,
// A-frags via plain ldsm4. K chunks of 64, 4-stage cp.async with tail commits.
// 8 warps = 4(m:q) x 2(n:k).
// ===========================================================================
#define SC_P 72
#define SC_QP 72
#define SC_STG_H (64*SC_P)     // 4608 halves
#define SC_SMEM (4*SC_STG_H*2) // 36864 B

__global__ void __launch_bounds__(256)
scores_h(const float* __restrict__ qmask, const float* __restrict__ kmask)
{
    extern __shared__ __half sh[];
    __shared__ __half Qs[64*SC_QP];   // [q][d]
    __shared__ float lw[4][2][16];

    const int b = blockIdx.z, h = blockIdx.y, q0 = blockIdx.x * 64;
    const __half* Q = g_qp + ((size_t)b * EE + h * DHH) * TT;
    const __half* K = g_kp + ((size_t)b * EE + h * DHH) * TT;
    __half* P = g_att + (size_t)(b * HH + h) * TT * TT;

    const int tid = threadIdx.x, lane = tid & 31, warp = tid >> 5;
    const int g = lane >> 2, t4 = lane & 3;
    const int wm = warp >> 1, wn = warp & 1;
    const int l15 = lane & 15, lhi = (lane >> 4) * 8;
    const int wq = wm * 16;

    auto issueK = [&](int s) {
        int kc = s * 64;
        unsigned kb = smaddr(sh + (s & 3) * SC_STG_H);
        #pragma unroll
        for (int l = 0; l < 2; l++) {
            int idx = tid + l * 256;
            int d = idx >> 3, c8 = (idx & 7) * 8;
            cpa16(kb + (d * SC_P + c8) * 2, K + (size_t)d * TT + kc + c8);
        }
        cpa_commit();
    };

    issueK(0); issueK(1); issueK(2);

    // stage Q tile transposed: Qs[q][d]
    #pragma unroll
    for (int l = 0; l < 8; l++) {
        int idx = tid + l * 256;        // [0,2048) __half2 over 64d x 64q
        int d = idx >> 5, q2 = (idx & 31) * 2;
        __half2 v = *(const __half2*)&Q[(size_t)d * TT + q0 + q2];
        Qs[(q2+0)*SC_QP + d] = __low2half(v);
        Qs[(q2+1)*SC_QP + d] = __high2half(v);
    }
    __syncthreads();

    // Q fragments resident for 4 ksteps (d = 0..63 by 16), non-trans ldsm
    unsigned areg[4][4];
    const unsigned qsa = smaddr(Qs);
    #pragma unroll
    for (int ks = 0; ks < 4; ks++)
        ldsm4(areg[ks], qsa + ((wq + l15) * SC_QP + ks*16 + lhi) * 2);

    const float qm0 = qmask[(size_t)b * TT + q0 + wq + g];
    const float qm1 = qmask[(size_t)b * TT + q0 + wq + g + 8];
    float l0 = 0.f, l1 = 0.f;

    const int NS = TT / 64;  // 32
    for (int s = 0; s < NS; s++) {
        cpa_wait<2>();
        __syncthreads();
        unsigned ksa = smaddr(sh + (s & 3) * SC_STG_H);

        float sc[4][4];
        #pragma unroll
        for (int nt = 0; nt < 4; nt++)
            #pragma unroll
            for (int e = 0; e < 4; e++) sc[nt][e] = 0.f;

        #pragma unroll
        for (int ks = 0; ks < 4; ks++) {
            unsigned bf[4][2];
            #pragma unroll
            for (int nb = 0; nb < 2; nb++) {
                unsigned r[4];
                ldsm4t(r, ksa + ((ks*16 + l15) * SC_P + wn*32 + nb*16 + lhi) * 2);
                bf[2*nb][0]   = r[0]; bf[2*nb][1]   = r[1];
                bf[2*nb+1][0] = r[2]; bf[2*nb+1][1] = r[3];
            }
            #pragma unroll
            for (int nt = 0; nt < 4; nt++)
                mma16(sc[nt], areg[ks], bf[nt]);
        }

        const int kc = s * 64;
        #pragma unroll
        for (int nt = 0; nt < 4; nt++) {
            int kcol = wn * 32 + nt * 8 + 2 * t4;
            float km0 = kmask[(size_t)b * TT + kc + kcol];
            float km1 = kmask[(size_t)b * TT + kc + kcol + 1];
            float e00 = __expf(sc[nt][0] * (qm0 * km0 * SCALE));
            float e01 = __expf(sc[nt][1] * (qm0 * km1 * SCALE));
            float e10 = __expf(sc[nt][2] * (qm1 * km0 * SCALE));
            float e11 = __expf(sc[nt][3] * (qm1 * km1 * SCALE));
            l0 += e00 + e01;
            l1 += e10 + e11;
            size_t r0 = (size_t)(q0 + wq + g) * TT + kc + kcol;
            size_t r1 = (size_t)(q0 + wq + g + 8) * TT + kc + kcol;
            *(__half2*)&P[r0] = __floats2half2_rn(e00 * km0, e01 * km1);
            *(__half2*)&P[r1] = __floats2half2_rn(e10 * km0, e11 * km1);
        }

        if (s + 3 < NS) issueK(s + 3);
        else            cpa_commit();      // tail: empty group
    }

    l0 += __shfl_xor_sync(0xffffffffu, l0, 1);
    l0 += __shfl_xor_sync(0xffffffffu, l0, 2);
    l1 += __shfl_xor_sync(0xffffffffu, l1, 1);
    l1 += __shfl_xor_sync(0xffffffffu, l1, 2);
    if (t4 == 0) { lw[wm][wn][g] = l0; lw[wm][wn][g + 8] = l1; }
    __syncthreads();
    if (tid < 64) {
        float l = lw[tid >> 4][0][tid & 15] + lw[tid >> 4][1][tid & 15];
        g_rl[(size_t)(b * HH + h) * TT + q0 + tid] = 1.0f / l;
    }
}

// ===========================================================================
// vscale: V'[b,e,q] = V[b,e,q] * rl[b, e>>6, q]  (fp16 out)
// ===========================================================================
__global__ void __launch_bounds__(256)
vscale_kernel()
{
    size_t i4 = ((size_t)blockIdx.x * 256 + threadIdx.x) * 4;
    int row = (int)(i4 / TT);   // b*EE + e
    int qq  = (int)(i4 % TT);
    int b = row >> 10, e = row & 1023, h = e >> 6;
    float4 r = *(const float4*)&g_rl[((size_t)(b * HH + h)) * TT + qq];
    float2 f01 = __half22float2(*(__half2*)&g_vp[i4]);
    float2 f23 = __half22float2(*(__half2*)&g_vp[i4 + 2]);
    *(__half2*)&g_vs[i4]     = __floats2half2_rn(f01.x * r.x, f01.y * r.y);
    *(__half2*)&g_vs[i4 + 2] = __floats2half2_rn(f23.x * r.z, f23.y * r.w);
}

// ===========================================================================
// AV: O[d,k] = sum_q V'[d,q] P[q,k].  64(d)x128(k) tile, q staged 32,
// 4-stage cp.async with tail commits. 8 warps = 2(m) x 4(n).
// Stage: A[64][40]h + B[32][136]h.
// ===========================================================================
#define AV_AP 40
#define AV_BP 136
#define AV_A_H (64*AV_AP)                // 2560
#define AV_STG_H (AV_A_H + 32*AV_BP)     // 6912 halves
#define AV_SMEM (4*AV_STG_H*2)           // 55296 B

__global__ void __launch_bounds__(256)
av_h()
{
    extern __shared__ __half sh[];
    const int b = blockIdx.z, h = blockIdx.y, k0 = blockIdx.x * 128;
    const __half* V = g_vs + ((size_t)b * EE + h * DHH) * TT;
    const __half* P = g_att + (size_t)(b * HH + h) * TT * TT;
    __half* O = g_oh + ((size_t)b * EE + h * DHH) * TT;

    const int tid = threadIdx.x, lane = tid & 31, warp = tid >> 5;
    const int g = lane >> 2, t4 = lane & 3;
    const int wm = warp >> 2, wn = warp & 3;
    const int l15 = lane & 15, lhi = (lane >> 4) * 8;

    float acc[2][4][4];
    #pragma unroll
    for (int i = 0; i < 2; i++)
        #pragma unroll
        for (int j = 0; j < 4; j++)
            #pragma unroll
            for (int e = 0; e < 4; e++) acc[i][j][e] = 0.f;

    auto issue = [&](int s) {
        int qc = s * 32;
        unsigned ab = smaddr(sh + (s & 3) * AV_STG_H);
        unsigned bb = ab + AV_A_H * 2;
        {   // V' tile: 64 rows x 32 halves = 256 chunks, 1/thread
            int r = tid >> 2, c8 = (tid & 3) * 8;
            cpa16(ab + (r * AV_AP + c8) * 2, V + (size_t)r * TT + qc + c8);
        }
        #pragma unroll
        for (int l = 0; l < 2; l++) {   // P tile: 32 x 128 halves = 512 chunks
            int idx = tid + l * 256;
            int r = idx >> 4, c8 = (idx & 15) * 8;
            cpa16(bb + (r * AV_BP + c8) * 2, P + (size_t)(qc + r) * TT + k0 + c8);
        }
        cpa_commit();
    };

    const int NS = TT / 32;   // 64
    issue(0); issue(1); issue(2);

    for (int s = 0; s < NS; s++) {
        cpa_wait<2>();
        __syncthreads();
        unsigned ab = smaddr(sh + (s & 3) * AV_STG_H);
        unsigned bb = ab + AV_A_H * 2;
        #pragma unroll
        for (int ks = 0; ks < 2; ks++) {
            unsigned a[2][4], bf[4][2];
            #pragma unroll
            for (int mt = 0; mt < 2; mt++)
                ldsm4(a[mt], ab + ((wm*32 + mt*16 + l15) * AV_AP + ks*16 + lhi) * 2);
            #pragma unroll
            for (int nb = 0; nb < 2; nb++) {
                unsigned r[4];
                ldsm4t(r, bb + ((ks*16 + l15) * AV_BP + wn*32 + nb*16 + lhi) * 2);
                bf[2*nb][0]   = r[0]; bf[2*nb][1]   = r[1];
                bf[2*nb+1][0] = r[2]; bf[2*nb+1][1] = r[3];
            }
            #pragma unroll
            for (int mt = 0; mt < 2; mt++)
                #pragma unroll
                for (int nt = 0; nt < 4; nt++)
                    mma16(acc[mt][nt], a[mt], bf[nt]);
        }
        if (s + 3 < NS) issue(s + 3);
        else            cpa_commit();      // tail: empty group
    }

    #pragma unroll
    for (int mt = 0; mt < 2; mt++) {
        int d = wm * 32 + mt * 16 + g;
        #pragma unroll
        for (int nt = 0; nt < 4; nt++) {
            int kcol = k0 + wn * 32 + nt * 8 + 2 * t4;
            *(__half2*)&O[(size_t)d * TT + kcol] =
                __floats2half2_rn(acc[mt][nt][0], acc[mt][nt][1]);
            *(__half2*)&O[(size_t)(d + 8) * TT + kcol] =
                __floats2half2_rn(acc[mt][nt][2], acc[mt][nt][3]);
        }
    }
}

// ===========================================================================
extern "C" void kernel_launch(void* const* d_in, const int* in_sizes, int n_in,
                              void* d_out, int out_size)
{
    const float* q   = (const float*)d_in[0];
    const float* k   = (const float*)d_in[1];
    const float* v   = (const float*)d_in[2];
    const float* qm  = (const float*)d_in[3];
    const float* km  = (const float*)d_in[4];
    const float* vm  = (const float*)d_in[5];
    const float* Wq  = (const float*)d_in[6];
    const float* bq  = (const float*)d_in[7];
    const float* Wk  = (const float*)d_in[8];
    const float* bk  = (const float*)d_in[9];
    const float* Wv  = (const float*)d_in[10];
    const float* bv  = (const float*)d_in[11];
    const float* Wo  = (const float*)d_in[12];
    const float* bo  = (const float*)d_in[13];
    float* out = (float*)d_out;

    cudaFuncSetAttribute(conv3_kernel,      cudaFuncAttributeMaxDynamicSharedMemorySize, CV_SMEM);
    cudaFuncSetAttribute(conv_final_kernel, cudaFuncAttributeMaxDynamicSharedMemorySize, CV_SMEM);
    cudaFuncSetAttribute(scores_h,          cudaFuncAttributeMaxDynamicSharedMemorySize, SC_SMEM);
    cudaFuncSetAttribute(av_h,              cudaFuncAttributeMaxDynamicSharedMemorySize, AV_SMEM);

    cvt_in<<<dim3(BB*EE*TT/1024, 1, 3), 256>>>(q, k, v);
    cvt_w <<<dim3(EE*EE/1024,    1, 4), 256>>>(Wq, Wk, Wv, Wo);

    dim3 g1(TT / 128, EE / 128, 3 * BB);
    conv3_kernel<<<g1, 256, CV_SMEM>>>(qm, km, vm, bq, bk, bv);

    dim3 g2(TT / 64, HH, BB);
    scores_h<<<g2, 256, SC_SMEM>>>(qm, km);

    vscale_kernel<<<BB*EE*TT/1024, 256>>>();

    dim3 g3(TT / 128, HH, BB);
    av_h<<<g3, 256, AV_SMEM>>>();

    dim3 g4(TT / 128, EE / 128, BB);
    conv_final_kernel<<<g4, 256, CV_SMEM>>>(bo, km, out);
}